// round 12
// baseline (speedup 1.0000x reference)
#include <cuda_runtime.h>
#include <cuda_bf16.h>
#include <math.h>
#include <stdint.h>

#define BB 2
#define LL 4096
#define DD 1024
#define HH 4
#define DV 256
#define NP 5
#define NC 128
#define BLROWS (BB*LL)
#define RIN 1144
#define RH 2288

// ---------------- scratch ----------------
__device__ float g_qlin[BLROWS*DD];
__device__ float g_klin[BLROWS*DD];
__device__ float g_vlin[BLROWS*DD];
__device__ float g_q[BLROWS*DD];
__device__ float g_k[BLROWS*DD];
__device__ float g_v[BLROWS*DD];
__device__ float g_beta[BLROWS*HH];
__device__ float g_qn[BLROWS*DD];
__device__ float g_kn[BLROWS*DD];
__device__ float g_u[BLROWS*DD];
__device__ float g_w[BLROWS*DD];
__device__ float g_la[BB*HH*NC*32*32];
__device__ float g_br0[BLROWS*DD];
__device__ float g_br1[BLROWS*DD];
__device__ float g_br2[BLROWS*DD];
__device__ float g_br3[BLROWS*DD];
__device__ float g_br4[BLROWS*DD];
__device__ float g_rin[BLROWS*RIN];
__device__ float g_hrt[BLROWS*RH];
__device__ float g_mix[BLROWS*DD];

__device__ __forceinline__ const float* branch_ptr(int p) {
    switch (p) {
        case 0: return g_br0;
        case 1: return g_br1;
        case 2: return g_br2;
        case 3: return g_br3;
        default: return g_br4;
    }
}
__device__ __forceinline__ float wred_sum(float v) {
    #pragma unroll
    for (int o = 16; o > 0; o >>= 1) v += __shfl_xor_sync(0xffffffffu, v, o);
    return v;
}
__device__ __forceinline__ float wred_max(float v) {
    #pragma unroll
    for (int o = 16; o > 0; o >>= 1) v = fmaxf(v, __shfl_xor_sync(0xffffffffu, v, o));
    return v;
}
__device__ __forceinline__ void mma_tf32(float c[4], const uint32_t a[4], const uint32_t b[2]) {
    asm volatile("mma.sync.aligned.m16n8k8.row.col.f32.tf32.tf32.f32 "
        "{%0,%1,%2,%3}, {%4,%5,%6,%7}, {%8,%9}, {%0,%1,%2,%3};\n"
        : "+f"(c[0]), "+f"(c[1]), "+f"(c[2]), "+f"(c[3])
        : "r"(a[0]), "r"(a[1]), "r"(a[2]), "r"(a[3]), "r"(b[0]), "r"(b[1]));
}
__device__ __forceinline__ uint32_t smem_u32(const void* p) {
    return (uint32_t)__cvta_generic_to_shared(p);
}
__device__ __forceinline__ void cp_async16(uint32_t dst, const void* src, int src_bytes) {
    asm volatile("cp.async.cg.shared.global [%0], [%1], 16, %2;"
                 :: "r"(dst), "l"(src), "r"(src_bytes));
}

// ---------------- TF32 tensor GEMM: 256x128 block, 64x64 warp tiles, 2 stages ----------------
#define TBM 256
#define TBN 128
#define TBK 32
#define TPAD 36
#define GEMM_SMEM ((2*TBM*TPAD + 2*TBN*TPAD)*4)

template<bool GELU>
__global__ __launch_bounds__(256) void tf32gemm_kernel(
    const float* __restrict__ A,
    const float* __restrict__ B0, const float* __restrict__ B1, const float* __restrict__ B2,
    const float* __restrict__ bias,
    float* __restrict__ C0, float* __restrict__ C1, float* __restrict__ C2,
    int M, int N, int K)
{
    const float* Bw = (blockIdx.z == 0) ? B0 : ((blockIdx.z == 1) ? B1 : B2);
    float* C       = (blockIdx.z == 0) ? C0 : ((blockIdx.z == 1) ? C1 : C2);

    extern __shared__ float gsm[];
    float* As = gsm;                       // [2][256][36]
    float* Bs = gsm + 2*TBM*TPAD;          // [2][128][36]
    int tid = threadIdx.x;
    int wid = tid >> 5, lane = tid & 31;
    int m_warp = (wid >> 1) * 64;          // 4 warps in m
    int n_warp = (wid & 1) * 64;           // 2 warps in n
    int bm = blockIdx.y * TBM, bn = blockIdx.x * TBN;

    float c[4][8][4];
    #pragma unroll
    for (int mt = 0; mt < 4; mt++)
        #pragma unroll
        for (int nt = 0; nt < 8; nt++)
            #pragma unroll
            for (int e = 0; e < 4; e++) c[mt][nt][e] = 0.f;

    int nT = (K + TBK - 1) / TBK;

    auto issue = [&](int kt) {
        int st = kt & 1;
        #pragma unroll
        for (int e = 0; e < 8; e++) {       // A: 256 rows x 8 chunks
            int idx = e * 256 + tid;
            int r = idx >> 3, cc = idx & 7;
            int kcol = kt * TBK + cc * 4;
            int vb = (kcol + 4 <= K) ? 16 : 0;
            int kc = vb ? kcol : 0;
            cp_async16(smem_u32(&As[(st*TBM + r)*TPAD + cc*4]),
                       A + (size_t)(bm + r) * K + kc, vb);
        }
        #pragma unroll
        for (int e = 0; e < 4; e++) {       // B: 128 rows x 8 chunks
            int idx = e * 256 + tid;
            int r = idx >> 3, cc = idx & 7;
            int kcol = kt * TBK + cc * 4;
            int vb = (kcol + 4 <= K) ? 16 : 0;
            int kc = vb ? kcol : 0;
            int brow = bn + r;
            int bb = (brow < N) ? vb : 0;
            int br = (brow < N) ? brow : 0;
            cp_async16(smem_u32(&Bs[(st*TBN + r)*TPAD + cc*4]),
                       Bw + (size_t)br * K + kc, bb);
        }
        asm volatile("cp.async.commit_group;");
    };

    issue(0);

    int ar = lane >> 2, ac = lane & 3;
    for (int kt = 0; kt < nT; kt++) {
        if (kt + 1 < nT) issue(kt + 1);
        else asm volatile("cp.async.commit_group;");
        asm volatile("cp.async.wait_group 1;");
        __syncthreads();
        int buf = kt & 1;
        const uint32_t* uA = reinterpret_cast<const uint32_t*>(As + buf*TBM*TPAD);
        const uint32_t* uB = reinterpret_cast<const uint32_t*>(Bs + buf*TBN*TPAD);
        #pragma unroll
        for (int ks = 0; ks < 4; ks++) {
            int k0 = ks * 8;
            uint32_t af[4][4], bf[8][2];
            #pragma unroll
            for (int mt = 0; mt < 4; mt++) {
                int rb = m_warp + mt * 16;
                af[mt][0] = uA[(rb + ar)*TPAD + k0 + ac];
                af[mt][1] = uA[(rb + ar + 8)*TPAD + k0 + ac];
                af[mt][2] = uA[(rb + ar)*TPAD + k0 + ac + 4];
                af[mt][3] = uA[(rb + ar + 8)*TPAD + k0 + ac + 4];
            }
            #pragma unroll
            for (int nt = 0; nt < 8; nt++) {
                int nb = n_warp + nt * 8;
                bf[nt][0] = uB[(nb + ar)*TPAD + k0 + ac];
                bf[nt][1] = uB[(nb + ar)*TPAD + k0 + ac + 4];
            }
            #pragma unroll
            for (int mt = 0; mt < 4; mt++)
                #pragma unroll
                for (int nt = 0; nt < 8; nt++)
                    mma_tf32(c[mt][nt], af[mt], bf[nt]);
        }
        __syncthreads();
    }

    int cr = lane >> 2, cc = (lane & 3) * 2;
    #pragma unroll
    for (int mt = 0; mt < 4; mt++) {
        size_t r0 = (size_t)(bm + m_warp + mt * 16 + cr);
        #pragma unroll
        for (int nt = 0; nt < 8; nt++) {
            int col = bn + n_warp + nt * 8 + cc;
            if (col < N) {
                float v0 = c[mt][nt][0], v1 = c[mt][nt][1];
                float v2 = c[mt][nt][2], v3 = c[mt][nt][3];
                if (GELU) {
                    float b0v = bias[col], b1v = bias[col + 1];
                    v0 += b0v; v1 += b1v; v2 += b0v; v3 += b1v;
                    v0 = 0.5f * v0 * (1.0f + erff(v0 * 0.70710678118654752f));
                    v1 = 0.5f * v1 * (1.0f + erff(v1 * 0.70710678118654752f));
                    v2 = 0.5f * v2 * (1.0f + erff(v2 * 0.70710678118654752f));
                    v3 = 0.5f * v3 * (1.0f + erff(v3 * 0.70710678118654752f));
                }
                *reinterpret_cast<float2*>(C + r0 * N + col) = make_float2(v0, v1);
                *reinterpret_cast<float2*>(C + (r0 + 8) * N + col) = make_float2(v2, v3);
            }
        }
    }
}

// ---------------- beta = sigmoid(hs @ Wb^T) ----------------
__global__ __launch_bounds__(128) void beta_kernel(const float* __restrict__ hs,
                                                   const float* __restrict__ Wb)
{
    int row = blockIdx.x;
    int w = threadIdx.x >> 5, lane = threadIdx.x & 31;
    const float* xr = hs + (size_t)row * DD;
    const float* wr = Wb + (size_t)w * DD;
    float acc = 0.f;
    for (int d = lane; d < DD; d += 32) acc += xr[d] * wr[d];
    acc = wred_sum(acc);
    if (lane == 0) g_beta[row * HH + w] = 1.f / (1.f + __expf(-acc));
}

// ---------------- fused depthwise causal conv K=4 + silu (float4) ----------------
__global__ __launch_bounds__(256) void dwconv3_kernel(
    const float* __restrict__ x0, const float* __restrict__ x1, const float* __restrict__ x2,
    const float* __restrict__ w0, const float* __restrict__ w1, const float* __restrict__ w2,
    float* __restrict__ y0, float* __restrict__ y1, float* __restrict__ y2)
{
    const float* x; const float* w; float* y;
    if (blockIdx.z == 0)      { x = x0; w = w0; y = y0; }
    else if (blockIdx.z == 1) { x = x1; w = w1; y = y1; }
    else                      { x = x2; w = w2; y = y2; }
    int idx = blockIdx.x * 256 + threadIdx.x;
    int c = (idx & 255) * 4;
    int row = idx >> 8;
    int l = row & (LL - 1);
    float4 wv0 = *reinterpret_cast<const float4*>(&w[(c+0)*4]);
    float4 wv1 = *reinterpret_cast<const float4*>(&w[(c+1)*4]);
    float4 wv2 = *reinterpret_cast<const float4*>(&w[(c+2)*4]);
    float4 wv3 = *reinterpret_cast<const float4*>(&w[(c+3)*4]);
    const float* pw0 = &wv0.x; const float* pw1 = &wv1.x;
    const float* pw2 = &wv2.x; const float* pw3 = &wv3.x;
    float4 acc = make_float4(0.f,0.f,0.f,0.f);
    #pragma unroll
    for (int j = 0; j < 4; j++) {
        int ll = l - 3 + j;
        if (ll >= 0) {
            float4 xv = *reinterpret_cast<const float4*>(&x[(size_t)(row - 3 + j) * DD + c]);
            acc.x = fmaf(xv.x, pw0[j], acc.x);
            acc.y = fmaf(xv.y, pw1[j], acc.y);
            acc.z = fmaf(xv.z, pw2[j], acc.z);
            acc.w = fmaf(xv.w, pw3[j], acc.w);
        }
    }
    acc.x = acc.x / (1.f + __expf(-acc.x));
    acc.y = acc.y / (1.f + __expf(-acc.y));
    acc.z = acc.z / (1.f + __expf(-acc.z));
    acc.w = acc.w / (1.f + __expf(-acc.w));
    *reinterpret_cast<float4*>(&y[(size_t)row * DD + c]) = acc;
}

// ---------------- delta stage A: 2-row register blocking + d-split ----------------
#define PADA 260
#define SA_QS 0
#define SA_KS (32*PADA)
#define SA_AT (64*PADA)
#define SA_BE (64*PADA + 1056)
#define SA_RN (64*PADA + 1088)
#define SA_SC (64*PADA + 1152)
#define SA_FLOATS (64*PADA + 1152 + 1024)
__global__ __launch_bounds__(256) void stageA_kernel()
{
    extern __shared__ float sm[];
    float* q_s  = sm + SA_QS;
    float* k_s  = sm + SA_KS;
    float* attn = sm + SA_AT;
    float* be_s = sm + SA_BE;
    float* rn_s = sm + SA_RN;
    float* sc_s = sm + SA_SC;

    int t = threadIdx.x;
    int ci = blockIdx.x, h = blockIdx.y, b = blockIdx.z;
    size_t rowbase = (size_t)b * LL + (size_t)ci * 32;
    size_t col0 = (size_t)h * DV;

    int dhalf = t >> 7;
    int tt = t & 127;
    int i0 = tt >> 3;
    int jg = tt & 7;
    int dbase = dhalf * 128;

    #pragma unroll
    for (int e = 0; e < 8; e++) {
        int idx = e*256 + t;
        int i = idx >> 6, c = (idx & 63) * 4;
        *reinterpret_cast<float4*>(&q_s[i*PADA + c]) =
            *reinterpret_cast<const float4*>(&g_q[(rowbase+i)*DD + col0 + c]);
        *reinterpret_cast<float4*>(&k_s[i*PADA + c]) =
            *reinterpret_cast<const float4*>(&g_k[(rowbase+i)*DD + col0 + c]);
    }
    if (t < 32) be_s[t] = g_beta[(rowbase + t) * HH + h];
    __syncthreads();

    {
        int r = t >> 3, g = t & 7;
        float sq = 0.f, sk = 0.f;
        #pragma unroll
        for (int dd = 0; dd < 32; dd++) {
            float a = q_s[r*PADA + g + 8*dd]; sq += a*a;
            float c2 = k_s[r*PADA + g + 8*dd]; sk += c2*c2;
        }
        #pragma unroll
        for (int o = 4; o > 0; o >>= 1) {
            sq += __shfl_xor_sync(0xffffffffu, sq, o);
            sk += __shfl_xor_sync(0xffffffffu, sk, o);
        }
        if (g == 0) { rn_s[r] = rsqrtf(sq + 1e-12f); rn_s[32+r] = rsqrtf(sk + 1e-12f); }
    }
    __syncthreads();
    #pragma unroll
    for (int e = 0; e < 8; e++) {
        int idx = e*256 + t;
        int i = idx >> 6, c = (idx & 63) * 4;
        float rq = rn_s[i], rk = rn_s[32+i];
        float4 qv = *reinterpret_cast<float4*>(&q_s[i*PADA + c]);
        qv.x *= rq; qv.y *= rq; qv.z *= rq; qv.w *= rq;
        *reinterpret_cast<float4*>(&q_s[i*PADA + c]) = qv;
        float4 kv = *reinterpret_cast<float4*>(&k_s[i*PADA + c]);
        kv.x *= rk; kv.y *= rk; kv.z *= rk; kv.w *= rk;
        *reinterpret_cast<float4*>(&k_s[i*PADA + c]) = kv;
    }
    __syncthreads();

    size_t chbase = (((size_t)b * HH + h) * NC + ci) * (32 * DV);
    size_t labase = (((size_t)b * HH + h) * NC + ci) * 1024;

    {
        float acc0[4] = {0.f,0.f,0.f,0.f};
        float acc1[4] = {0.f,0.f,0.f,0.f};
        for (int d = 0; d < 128; d += 4) {
            float4 q0 = *reinterpret_cast<const float4*>(&q_s[i0*PADA + dbase + d]);
            float4 q1 = *reinterpret_cast<const float4*>(&q_s[(i0+16)*PADA + dbase + d]);
            #pragma unroll
            for (int jj = 0; jj < 4; jj++) {
                float4 kv = *reinterpret_cast<const float4*>(&k_s[(jg + 8*jj)*PADA + dbase + d]);
                acc0[jj] = fmaf(q0.x, kv.x, acc0[jj]);
                acc0[jj] = fmaf(q0.y, kv.y, acc0[jj]);
                acc0[jj] = fmaf(q0.z, kv.z, acc0[jj]);
                acc0[jj] = fmaf(q0.w, kv.w, acc0[jj]);
                acc1[jj] = fmaf(q1.x, kv.x, acc1[jj]);
                acc1[jj] = fmaf(q1.y, kv.y, acc1[jj]);
                acc1[jj] = fmaf(q1.z, kv.z, acc1[jj]);
                acc1[jj] = fmaf(q1.w, kv.w, acc1[jj]);
            }
        }
        if (dhalf == 1) {
            #pragma unroll
            for (int jj = 0; jj < 4; jj++) {
                sc_s[tt*8 + jj]     = acc0[jj];
                sc_s[tt*8 + 4 + jj] = acc1[jj];
            }
        }
        __syncthreads();
        if (dhalf == 0) {
            #pragma unroll
            for (int jj = 0; jj < 4; jj++) {
                float v0 = acc0[jj] + sc_s[tt*8 + jj];
                float v1 = acc1[jj] + sc_s[tt*8 + 4 + jj];
                int j = jg + 8*jj;
                g_la[labase + i0*32 + j]      = (j <= i0)      ? v0 : 0.f;
                g_la[labase + (i0+16)*32 + j] = (j <= i0 + 16) ? v1 : 0.f;
            }
        }
    }
    __syncthreads();

    #pragma unroll
    for (int e = 0; e < 8; e++) {
        int idx = e*256 + t;
        int i = idx >> 6, c = (idx & 63) * 4;
        *reinterpret_cast<float4*>(&g_qn[chbase + i*DV + c]) =
            *reinterpret_cast<const float4*>(&q_s[i*PADA + c]);
        *reinterpret_cast<float4*>(&g_kn[chbase + i*DV + c]) =
            *reinterpret_cast<const float4*>(&k_s[i*PADA + c]);
        float4 vv = *reinterpret_cast<const float4*>(&g_v[(rowbase+i)*DD + col0 + c]);
        float be = be_s[i];
        vv.x *= be; vv.y *= be; vv.z *= be; vv.w *= be;
        *reinterpret_cast<float4*>(&q_s[i*PADA + c]) = vv;
    }
    __syncthreads();

    {
        float bi0 = be_s[i0], bi1 = be_s[i0 + 16];
        float acc0[4] = {0.f,0.f,0.f,0.f};
        float acc1[4] = {0.f,0.f,0.f,0.f};
        for (int d = 0; d < 128; d += 4) {
            float4 k0v = *reinterpret_cast<const float4*>(&k_s[i0*PADA + dbase + d]);
            k0v.x *= bi0; k0v.y *= bi0; k0v.z *= bi0; k0v.w *= bi0;
            float4 k1v = *reinterpret_cast<const float4*>(&k_s[(i0+16)*PADA + dbase + d]);
            k1v.x *= bi1; k1v.y *= bi1; k1v.z *= bi1; k1v.w *= bi1;
            #pragma unroll
            for (int jj = 0; jj < 4; jj++) {
                float4 kv = *reinterpret_cast<const float4*>(&k_s[(jg + 8*jj)*PADA + dbase + d]);
                acc0[jj] = fmaf(k0v.x, kv.x, acc0[jj]);
                acc0[jj] = fmaf(k0v.y, kv.y, acc0[jj]);
                acc0[jj] = fmaf(k0v.z, kv.z, acc0[jj]);
                acc0[jj] = fmaf(k0v.w, kv.w, acc0[jj]);
                acc1[jj] = fmaf(k1v.x, kv.x, acc1[jj]);
                acc1[jj] = fmaf(k1v.y, kv.y, acc1[jj]);
                acc1[jj] = fmaf(k1v.z, kv.z, acc1[jj]);
                acc1[jj] = fmaf(k1v.w, kv.w, acc1[jj]);
            }
        }
        if (dhalf == 1) {
            #pragma unroll
            for (int jj = 0; jj < 4; jj++) {
                sc_s[tt*8 + jj]     = acc0[jj];
                sc_s[tt*8 + 4 + jj] = acc1[jj];
            }
        }
        __syncthreads();
        if (dhalf == 0) {
            #pragma unroll
            for (int jj = 0; jj < 4; jj++) {
                float v0 = acc0[jj] + sc_s[tt*8 + jj];
                float v1 = acc1[jj] + sc_s[tt*8 + 4 + jj];
                int j = jg + 8*jj;
                attn[i0*33 + j]      = (i0 > j)      ? -v0 : 0.f;
                attn[(i0+16)*33 + j] = (i0 + 16 > j) ? -v1 : 0.f;
            }
        }
    }
    __syncthreads();

    if (t < 32) {
        int j = t;
        for (int i = 1; i < 32; i++) {
            float upd = 0.f;
            if (j < i)
                for (int k = j + 1; k < i; k++) upd += attn[i*33 + k] * attn[k*33 + j];
            __syncwarp();
            if (j < i) attn[i*33 + j] += upd;
            __syncwarp();
        }
        attn[j*33 + j] = 1.f;
    }
    __syncthreads();

    {
        int i = t >> 3, g = t & 7;
        float2 accu[16];
        #pragma unroll
        for (int dd = 0; dd < 16; dd++) accu[dd] = make_float2(0.f, 0.f);
        for (int k = 0; k < 32; k++) {
            float av = attn[i*33 + k];
            #pragma unroll
            for (int dd = 0; dd < 16; dd++) {
                float2 qv = *reinterpret_cast<const float2*>(&q_s[k*PADA + g*2 + dd*16]);
                accu[dd].x = fmaf(av, qv.x, accu[dd].x);
                accu[dd].y = fmaf(av, qv.y, accu[dd].y);
            }
        }
        #pragma unroll
        for (int dd = 0; dd < 16; dd++)
            *reinterpret_cast<float2*>(&g_u[chbase + i*DV + g*2 + dd*16]) = accu[dd];

        #pragma unroll
        for (int dd = 0; dd < 16; dd++) accu[dd] = make_float2(0.f, 0.f);
        for (int k = 0; k < 32; k++) {
            float av = attn[i*33 + k] * be_s[k];
            #pragma unroll
            for (int dd = 0; dd < 16; dd++) {
                float2 kv = *reinterpret_cast<const float2*>(&k_s[k*PADA + g*2 + dd*16]);
                accu[dd].x = fmaf(av, kv.x, accu[dd].x);
                accu[dd].y = fmaf(av, kv.y, accu[dd].y);
            }
        }
        #pragma unroll
        for (int dd = 0; dd < 16; dd++)
            *reinterpret_cast<float2*>(&g_w[chbase + i*DV + g*2 + dd*16]) = accu[dd];
    }
}

// ---------------- delta stage B + fused FIR/copy (512 threads) ----------------
#define SBW 264
#define SB2_W   0
#define SB2_Q   8448
#define SB2_K   16896
#define SB2_LA  25344
#define SB2_BUF 26368
#define SB2_S   52736
#define SB2_UI  57344
#define SB2_FLOATS 57856
#define BAR_SCAN() asm volatile("bar.sync 1, 256;" ::: "memory")

__global__ __launch_bounds__(512) void stageB_kernel(
    const float* __restrict__ w3, const float* __restrict__ w7,
    const float* __restrict__ w25, const float* __restrict__ w1,
    const float* __restrict__ hs)
{
    extern __shared__ float sm[];
    int t = threadIdx.x;
    int js = blockIdx.x, h = blockIdx.y, b = blockIdx.z;

    if (t >= 256) {
        int lt = t - 256;
        int blockLin = js + 16 * h + 64 * b;
        int rbase = blockLin * 64;

        for (int r = 0; r < 64; r++) {
            int row = rbase + r;
            *reinterpret_cast<float4*>(&g_rin[(size_t)row * RIN + lt*4]) =
                *reinterpret_cast<const float4*>(&hs[(size_t)row * DD + lt*4]);
        }

        for (int cho = 0; cho < 4; cho++) {
            int c = cho * 256 + lt;
            float fw3[3], fw7[7], fw25[25], fw1;
            #pragma unroll
            for (int j = 0; j < 3; j++)  fw3[j]  = w3[c*3 + j];
            #pragma unroll
            for (int j = 0; j < 7; j++)  fw7[j]  = w7[c*7 + j];
            #pragma unroll
            for (int j = 0; j < 25; j++) fw25[j] = w25[c*25 + j];
            fw1 = w1[c];
            for (int r = 0; r < 64; r++) {
                int row = rbase + r;
                int l = row & (LL - 1);
                float x[25];
                #pragma unroll
                for (int tt = 0; tt < 25; tt++)
                    x[tt] = (l - tt >= 0) ? g_v[(size_t)(row - tt) * DD + c] : 0.f;
                float a3 = 0.f, a7 = 0.f, a25 = 0.f;
                #pragma unroll
                for (int j = 0; j < 3; j++)  a3  += fw3[j]  * x[2  - j];
                #pragma unroll
                for (int j = 0; j < 7; j++)  a7  += fw7[j]  * x[6  - j];
                #pragma unroll
                for (int j = 0; j < 25; j++) a25 += fw25[j] * x[24 - j];
                size_t oi = (size_t)row * DD + c;
                g_br0[oi] = a3;
                g_br1[oi] = a7;
                g_br2[oi] = a25;
                g_br4[oi] = fw1 * x[0];
            }
        }
        return;
    }

    float* S  = sm + SB2_S;
    float* ui = sm + SB2_UI;

    #pragma unroll
    for (int j = 0; j < 16; j++) S[t*18 + j] = 0.f;
    size_t bh = (size_t)b * HH + h;
    int ii = t >> 3, jc = t & 7;

    auto issue_chunk = [&](int ci) {
        float* buf = sm + (ci & 1) * SB2_BUF;
        size_t chb = (bh * NC + ci) * (32 * DV);
        #pragma unroll
        for (int e = 0; e < 8; e++) {
            int idx = e * 256 + t;
            int i = idx >> 6, cc = idx & 63;
            int goff = idx * 4;
            int soff = i * SBW + cc * 4;
            cp_async16(smem_u32(&buf[SB2_W + soff]), g_w  + chb + goff, 16);
            cp_async16(smem_u32(&buf[SB2_Q + soff]), g_qn + chb + goff, 16);
            cp_async16(smem_u32(&buf[SB2_K + soff]), g_kn + chb + goff, 16);
        }
        cp_async16(smem_u32(&buf[SB2_LA + t*4]), g_la + (bh * NC + ci) * 1024 + t*4, 16);
        asm volatile("cp.async.commit_group;");
    };

    issue_chunk(0);
    issue_chunk(1);
    float2 uv = *reinterpret_cast<const float2*>(
        &g_u[(bh * NC + 0) * (32 * DV) + (size_t)ii * DV + js*16 + 2*jc]);

    for (int ci = 0; ci < NC; ci++) {
        asm volatile("cp.async.wait_group %0;" :: "n"(1));
        BAR_SCAN();
        float* buf  = sm + (ci & 1) * SB2_BUF;
        float* w_s  = buf + SB2_W;
        float* q_s  = buf + SB2_Q;
        float* k_s  = buf + SB2_K;
        float* la_s = buf + SB2_LA;

        float2 uv_next = make_float2(0.f, 0.f);
        if (ci + 1 < NC)
            uv_next = *reinterpret_cast<const float2*>(
                &g_u[(bh * NC + ci + 1) * (32 * DV) + (size_t)ii * DV + js*16 + 2*jc]);

        float a0 = uv.x, a1 = uv.y, o0 = 0.f, o1 = 0.f;
        #pragma unroll 4
        for (int m = 0; m < 256; m += 2) {
            float2 wv = *reinterpret_cast<const float2*>(&w_s[ii*SBW + m]);
            float2 qv = *reinterpret_cast<const float2*>(&q_s[ii*SBW + m]);
            float2 s0 = *reinterpret_cast<const float2*>(&S[m*18 + 2*jc]);
            float2 s1 = *reinterpret_cast<const float2*>(&S[(m+1)*18 + 2*jc]);
            a0 = fmaf(-wv.x, s0.x, a0); a1 = fmaf(-wv.x, s0.y, a1);
            o0 = fmaf( qv.x, s0.x, o0); o1 = fmaf( qv.x, s0.y, o1);
            a0 = fmaf(-wv.y, s1.x, a0); a1 = fmaf(-wv.y, s1.y, a1);
            o0 = fmaf( qv.y, s1.x, o0); o1 = fmaf( qv.y, s1.y, o1);
        }
        ui[ii*16 + 2*jc]     = a0;
        ui[ii*16 + 2*jc + 1] = a1;
        BAR_SCAN();

        #pragma unroll
        for (int k = 0; k < 32; k++) {
            float lv = la_s[ii*32 + k];
            float2 uu = *reinterpret_cast<const float2*>(&ui[k*16 + 2*jc]);
            o0 = fmaf(lv, uu.x, o0); o1 = fmaf(lv, uu.y, o1);
        }
        size_t orow = ((size_t)b * LL + (size_t)ci*32 + ii) * DD + (size_t)h * DV + js*16 + 2*jc;
        *reinterpret_cast<float2*>(&g_br3[orow]) = make_float2(o0, o1);

        float acc[16];
        #pragma unroll
        for (int j = 0; j < 16; j++) acc[j] = 0.f;
        #pragma unroll 4
        for (int i = 0; i < 32; i++) {
            float kv = k_s[i*SBW + t];
            const float4* up = reinterpret_cast<const float4*>(&ui[i*16]);
            float4 u0 = up[0], u1 = up[1], u2 = up[2], u3 = up[3];
            acc[0]  = fmaf(kv, u0.x, acc[0]);  acc[1]  = fmaf(kv, u0.y, acc[1]);
            acc[2]  = fmaf(kv, u0.z, acc[2]);  acc[3]  = fmaf(kv, u0.w, acc[3]);
            acc[4]  = fmaf(kv, u1.x, acc[4]);  acc[5]  = fmaf(kv, u1.y, acc[5]);
            acc[6]  = fmaf(kv, u1.z, acc[6]);  acc[7]  = fmaf(kv, u1.w, acc[7]);
            acc[8]  = fmaf(kv, u2.x, acc[8]);  acc[9]  = fmaf(kv, u2.y, acc[9]);
            acc[10] = fmaf(kv, u2.z, acc[10]); acc[11] = fmaf(kv, u2.w, acc[11]);
            acc[12] = fmaf(kv, u3.x, acc[12]); acc[13] = fmaf(kv, u3.y, acc[13]);
            acc[14] = fmaf(kv, u3.z, acc[14]); acc[15] = fmaf(kv, u3.w, acc[15]);
        }
        #pragma unroll
        for (int j = 0; j < 16; j++) S[t*18 + j] += acc[j];

        BAR_SCAN();
        if (ci + 2 < NC) issue_chunk(ci + 2);
        else asm volatile("cp.async.commit_group;");
        uv = uv_next;
    }
}

// ---------------- branch stats (float4 loads) ----------------
__global__ __launch_bounds__(256) void stats_kernel()
{
    int gw = blockIdx.x * 8 + (threadIdx.x >> 5);
    int lane = threadIdx.x & 31;
    int row = gw >> 2, h = gw & 3;
    size_t base = (size_t)row * DD + (size_t)h * DV + lane * 8;
    float x[5][8];
    #pragma unroll
    for (int p = 0; p < 5; p++) {
        const float* bp = branch_ptr(p);
        float4 a = *reinterpret_cast<const float4*>(&bp[base]);
        float4 bq = *reinterpret_cast<const float4*>(&bp[base + 4]);
        x[p][0]=a.x; x[p][1]=a.y; x[p][2]=a.z; x[p][3]=a.w;
        x[p][4]=bq.x; x[p][5]=bq.y; x[p][6]=bq.z; x[p][7]=bq.w;
    }
    float ssv[5];
    float* rout = g_rin + (size_t)row * RIN;
    #pragma unroll
    for (int p = 0; p < 5; p++) {
        float s = 0.f, ss = 0.f, mx = -1e30f;
        #pragma unroll
        for (int e = 0; e < 8; e++) {
            float v = x[p][e];
            s += v; ss += v*v; mx = fmaxf(mx, v);
        }
        s = wred_sum(s); ss = wred_sum(ss); mx = wred_max(mx);
        float ez[8]; float Zp = 0.f;
        #pragma unroll
        for (int e = 0; e < 8; e++) { ez[e] = __expf(x[p][e] - mx); Zp += ez[e]; }
        float Z = wred_sum(Zp);
        float ep = 0.f;
        #pragma unroll
        for (int e = 0; e < 8; e++) { float smv = ez[e] / Z; ep += smv * __logf(smv + 1e-8f); }
        float ent = -wred_sum(ep);
        ssv[p] = ss;
        if (lane == 0) {
            rout[1024 + (p*4 + 0)*HH + h] = s * (1.f/256.f);
            rout[1024 + (p*4 + 1)*HH + h] = (ss - s*s*(1.f/256.f)) * (1.f/255.f);
            rout[1024 + (p*4 + 2)*HH + h] = mx;
            rout[1024 + (p*4 + 3)*HH + h] = ent;
        }
    }
    int c = 0;
    #pragma unroll
    for (int i = 0; i < 5; i++)
        #pragma unroll
        for (int j = i + 1; j < 5; j++) {
            float d = 0.f;
            #pragma unroll
            for (int e = 0; e < 8; e++) d += x[i][e] * x[j][e];
            d = wred_sum(d);
            if (lane == 0)
                rout[1104 + c*HH + h] = d / (sqrtf(ssv[i]) * sqrtf(ssv[j]) + 1e-8f);
            c++;
        }
}

// ---------------- logits + softmax floor + mix + RMSnorm : 8 rows per block ----------------
#define LMR 8
#define HPAD 2292
#define LM_SMEM (LMR*HPAD*4)
__global__ __launch_bounds__(256) void logits_mix_kernel(const float* __restrict__ W2,
                                                         const float* __restrict__ b2,
                                                         const float* __restrict__ norm_w)
{
    extern __shared__ float lsm[];
    __shared__ float lg_s[LMR][20];
    __shared__ float pr_s[LMR][20];
    __shared__ float wred_s[LMR][8];
    int t = threadIdx.x;
    int wid = t >> 5, lane = t & 31;
    int row0 = blockIdx.x * LMR;

    for (int idx = t; idx < LMR * 572; idx += 256) {
        int r = idx / 572, c4 = idx % 572;
        *reinterpret_cast<float4*>(&lsm[r*HPAD + c4*4]) =
            *reinterpret_cast<const float4*>(&g_hrt[(size_t)(row0 + r) * RH + c4*4]);
    }
    __syncthreads();

    {
        const float* hr = &lsm[wid*HPAD];
        for (int n = 0; n < 20; n++) {
            const float* w2r = W2 + (size_t)n * RH;
            float acc = 0.f;
            for (int idx = lane; idx < 572; idx += 32) {
                float4 hv = *reinterpret_cast<const float4*>(&hr[idx*4]);
                float4 wv = *reinterpret_cast<const float4*>(&w2r[idx*4]);
                acc += hv.x*wv.x + hv.y*wv.y + hv.z*wv.z + hv.w*wv.w;
            }
            acc = wred_sum(acc);
            if (lane == 0) lg_s[wid][n] = acc + b2[n];
        }
    }
    __syncthreads();
    if (t < 32) {
        int r = t >> 2, hh = t & 3;
        float m = -1e30f;
        #pragma unroll
        for (int p = 0; p < 5; p++) m = fmaxf(m, lg_s[r][hh*5 + p]);
        float Z = 0.f, e[5];
        #pragma unroll
        for (int p = 0; p < 5; p++) { e[p] = __expf(lg_s[r][hh*5 + p] - m); Z += e[p]; }
        #pragma unroll
        for (int p = 0; p < 5; p++) pr_s[r][hh*5 + p] = e[p] / Z * 0.95f + 0.01f;
    }
    __syncthreads();

    int c = t * 4;
    int hh = t >> 6;
    float4 nw4 = *reinterpret_cast<const float4*>(&norm_w[c & 255]);
    float4 val[LMR];
    #pragma unroll
    for (int r = 0; r < LMR; r++) {
        size_t base = (size_t)(row0 + r) * DD + c;
        float4 acc = make_float4(0.f,0.f,0.f,0.f);
        #pragma unroll
        for (int p = 0; p < 5; p++) {
            float4 bv = *reinterpret_cast<const float4*>(&branch_ptr(p)[base]);
            float pr = pr_s[r][hh*5 + p];
            acc.x = fmaf(pr, bv.x, acc.x);
            acc.y = fmaf(pr, bv.y, acc.y);
            acc.z = fmaf(pr, bv.z, acc.z);
            acc.w = fmaf(pr, bv.w, acc.w);
        }
        val[r] = acc;
        float sq = acc.x*acc.x + acc.y*acc.y + acc.z*acc.z + acc.w*acc.w;
        sq = wred_sum(sq);
        if (lane == 0) wred_s[r][wid] = sq;
    }
    __syncthreads();
    #pragma unroll
    for (int r = 0; r < LMR; r++) {
        float s = wred_s[r][hh*2] + wred_s[r][hh*2 + 1];
        float rms = rsqrtf(s * (1.f/256.f) + 1e-5f);
        float4 v = val[r];
        v.x *= rms * nw4.x; v.y *= rms * nw4.y;
        v.z *= rms * nw4.z; v.w *= rms * nw4.w;
        *reinterpret_cast<float4*>(&g_mix[(size_t)(row0 + r) * DD + c]) = v;
    }
}

// ---------------- launch ----------------
static float* sym(const void* s) { void* p = nullptr; cudaGetSymbolAddress(&p, s); return (float*)p; }

extern "C" void kernel_launch(void* const* d_in, const int* in_sizes, int n_in,
                              void* d_out, int out_size)
{
    const float* hs       = (const float*)d_in[0];
    const float* Wq       = (const float*)d_in[1];
    const float* Wk       = (const float*)d_in[2];
    const float* Wv       = (const float*)d_in[3];
    const float* wq_conv  = (const float*)d_in[4];
    const float* wk_conv  = (const float*)d_in[5];
    const float* wv_conv  = (const float*)d_in[6];
    const float* Wb       = (const float*)d_in[7];
    const float* fir_s_w  = (const float*)d_in[8];
    const float* fir_m_w  = (const float*)d_in[9];
    const float* fir_l_w  = (const float*)d_in[10];
    const float* fir_id_w = (const float*)d_in[11];
    const float* W1       = (const float*)d_in[12];
    const float* b1       = (const float*)d_in[13];
    const float* W2       = (const float*)d_in[14];
    const float* b2       = (const float*)d_in[15];
    const float* norm_w   = (const float*)d_in[16];
    const float* Wo       = (const float*)d_in[17];
    float* out = (float*)d_out;

    float* p_qlin = sym(g_qlin); float* p_klin = sym(g_klin); float* p_vlin = sym(g_vlin);
    float* p_q = sym(g_q); float* p_k = sym(g_k); float* p_v = sym(g_v);
    float* p_rin = sym(g_rin); float* p_hrt = sym(g_hrt); float* p_mix = sym(g_mix);

    cudaFuncSetAttribute(tf32gemm_kernel<false>, cudaFuncAttributeMaxDynamicSharedMemorySize, GEMM_SMEM);
    cudaFuncSetAttribute(tf32gemm_kernel<true>, cudaFuncAttributeMaxDynamicSharedMemorySize, GEMM_SMEM);
    cudaFuncSetAttribute(stageA_kernel, cudaFuncAttributeMaxDynamicSharedMemorySize, SA_FLOATS*4);
    cudaFuncSetAttribute(stageB_kernel, cudaFuncAttributeMaxDynamicSharedMemorySize, SB2_FLOATS*4);
    cudaFuncSetAttribute(logits_mix_kernel, cudaFuncAttributeMaxDynamicSharedMemorySize, LM_SMEM);

    beta_kernel<<<BLROWS, 128>>>(hs, Wb);
    tf32gemm_kernel<false><<<dim3(DD/TBN, BLROWS/TBM, 3), 256, GEMM_SMEM>>>(
        hs, Wq, Wk, Wv, nullptr, p_qlin, p_klin, p_vlin, BLROWS, DD, DD);

    int cg4 = BLROWS*DD/1024;
    dwconv3_kernel<<<dim3(cg4, 1, 3), 256>>>(p_qlin, p_klin, p_vlin,
                                             wq_conv, wk_conv, wv_conv,
                                             p_q, p_k, p_v);

    stageA_kernel<<<dim3(NC, HH, BB), 256, SA_FLOATS*4>>>();
    stageB_kernel<<<dim3(16, HH, BB), 512, SB2_FLOATS*4>>>(
        fir_s_w, fir_m_w, fir_l_w, fir_id_w, hs);

    stats_kernel<<<BLROWS*HH/8, 256>>>();

    tf32gemm_kernel<true><<<dim3((RH+TBN-1)/TBN, BLROWS/TBM, 1), 256, GEMM_SMEM>>>(
        p_rin, W1, W1, W1, b1, p_hrt, p_hrt, p_hrt, BLROWS, RH, RIN);
    logits_mix_kernel<<<BLROWS/LMR, 256, LM_SMEM>>>(W2, b2, norm_w);
    tf32gemm_kernel<false><<<dim3(DD/TBN, BLROWS/TBM, 1), 256, GEMM_SMEM>>>(
        p_mix, Wo, Wo, Wo, nullptr, out, out, out, BLROWS, DD, DD);
}

// round 15
// speedup vs baseline: 1.0170x; 1.0170x over previous
#include <cuda_runtime.h>
#include <cuda_bf16.h>
#include <math.h>
#include <stdint.h>

#define BB 2
#define LL 4096
#define DD 1024
#define HH 4
#define DV 256
#define NP 5
#define NC 128
#define BLROWS (BB*LL)
#define RIN 1144
#define RH 2288

// ---------------- scratch ----------------
__device__ float g_qlin[BLROWS*DD];
__device__ float g_klin[BLROWS*DD];
__device__ float g_vlin[BLROWS*DD];
__device__ float g_v[BLROWS*DD];
__device__ float g_beta[BLROWS*HH];
__device__ float g_qn[BLROWS*DD];
__device__ float g_kn[BLROWS*DD];
__device__ float g_u[BLROWS*DD];
__device__ float g_w[BLROWS*DD];
__device__ float g_la[BB*HH*NC*32*32];
__device__ float g_br0[BLROWS*DD];
__device__ float g_br1[BLROWS*DD];
__device__ float g_br2[BLROWS*DD];
__device__ float g_br3[BLROWS*DD];
__device__ float g_br4[BLROWS*DD];
__device__ float g_rin[BLROWS*RIN];
__device__ float g_hrt[BLROWS*RH];
__device__ float g_mix[BLROWS*DD];

__device__ __forceinline__ const float* branch_ptr(int p) {
    switch (p) {
        case 0: return g_br0;
        case 1: return g_br1;
        case 2: return g_br2;
        case 3: return g_br3;
        default: return g_br4;
    }
}
__device__ __forceinline__ float wred_sum(float v) {
    #pragma unroll
    for (int o = 16; o > 0; o >>= 1) v += __shfl_xor_sync(0xffffffffu, v, o);
    return v;
}
__device__ __forceinline__ float wred_max(float v) {
    #pragma unroll
    for (int o = 16; o > 0; o >>= 1) v = fmaxf(v, __shfl_xor_sync(0xffffffffu, v, o));
    return v;
}
__device__ __forceinline__ void mma_tf32(float c[4], const uint32_t a[4], const uint32_t b[2]) {
    asm volatile("mma.sync.aligned.m16n8k8.row.col.f32.tf32.tf32.f32 "
        "{%0,%1,%2,%3}, {%4,%5,%6,%7}, {%8,%9}, {%0,%1,%2,%3};\n"
        : "+f"(c[0]), "+f"(c[1]), "+f"(c[2]), "+f"(c[3])
        : "r"(a[0]), "r"(a[1]), "r"(a[2]), "r"(a[3]), "r"(b[0]), "r"(b[1]));
}
__device__ __forceinline__ uint32_t smem_u32(const void* p) {
    return (uint32_t)__cvta_generic_to_shared(p);
}
__device__ __forceinline__ void cp_async16(uint32_t dst, const void* src, int src_bytes) {
    asm volatile("cp.async.cg.shared.global [%0], [%1], 16, %2;"
                 :: "r"(dst), "l"(src), "r"(src_bytes));
}

// ---------------- TF32 tensor GEMM: TBK=32, 2 stages, raw f32 bits ----------------
#define TBM 128
#define TBN 128
#define TBK 32
#define TPAD 36
#define GEMM_SMEM (2*TBM*TPAD*2*4)

template<bool GELU>
__global__ __launch_bounds__(256) void tf32gemm_kernel(
    const float* __restrict__ A,
    const float* __restrict__ B0, const float* __restrict__ B1, const float* __restrict__ B2,
    const float* __restrict__ bias,
    float* __restrict__ C0, float* __restrict__ C1, float* __restrict__ C2,
    int M, int N, int K)
{
    const float* Bw = (blockIdx.z == 0) ? B0 : ((blockIdx.z == 1) ? B1 : B2);
    float* C       = (blockIdx.z == 0) ? C0 : ((blockIdx.z == 1) ? C1 : C2);

    extern __shared__ float gsm[];
    float* As = gsm;
    float* Bs = gsm + 2*TBM*TPAD;
    int tid = threadIdx.x;
    int wid = tid >> 5, lane = tid & 31;
    int m_warp = (wid >> 2) * 64;
    int n_warp = (wid & 3) * 32;
    int bm = blockIdx.y * TBM, bn = blockIdx.x * TBN;

    float c[4][4][4];
    #pragma unroll
    for (int mt = 0; mt < 4; mt++)
        #pragma unroll
        for (int nt = 0; nt < 4; nt++)
            #pragma unroll
            for (int e = 0; e < 4; e++) c[mt][nt][e] = 0.f;

    int nT = (K + TBK - 1) / TBK;

    auto issue = [&](int kt) {
        int st = kt & 1;
        #pragma unroll
        for (int e = 0; e < 4; e++) {
            int idx = e * 256 + tid;
            int r = idx >> 3, cc = idx & 7;
            int kcol = kt * TBK + cc * 4;
            int vb = (kcol + 4 <= K) ? 16 : 0;
            int kc = vb ? kcol : 0;
            cp_async16(smem_u32(&As[(st*TBM + r)*TPAD + cc*4]),
                       A + (size_t)(bm + r) * K + kc, vb);
            int brow = bn + r;
            int bb = (brow < N) ? vb : 0;
            int br = (brow < N) ? brow : 0;
            cp_async16(smem_u32(&Bs[(st*TBM + r)*TPAD + cc*4]),
                       Bw + (size_t)br * K + kc, bb);
        }
        asm volatile("cp.async.commit_group;");
    };

    issue(0);

    int ar = lane >> 2, ac = lane & 3;
    for (int kt = 0; kt < nT; kt++) {
        if (kt + 1 < nT) issue(kt + 1);
        else asm volatile("cp.async.commit_group;");
        asm volatile("cp.async.wait_group 1;");
        __syncthreads();
        int buf = kt & 1;
        const uint32_t* uA = reinterpret_cast<const uint32_t*>(As + buf*TBM*TPAD);
        const uint32_t* uB = reinterpret_cast<const uint32_t*>(Bs + buf*TBM*TPAD);
        #pragma unroll
        for (int ks = 0; ks < 4; ks++) {
            int k0 = ks * 8;
            uint32_t af[4][4], bf[4][2];
            #pragma unroll
            for (int mt = 0; mt < 4; mt++) {
                int rb = m_warp + mt * 16;
                af[mt][0] = uA[(rb + ar)*TPAD + k0 + ac];
                af[mt][1] = uA[(rb + ar + 8)*TPAD + k0 + ac];
                af[mt][2] = uA[(rb + ar)*TPAD + k0 + ac + 4];
                af[mt][3] = uA[(rb + ar + 8)*TPAD + k0 + ac + 4];
            }
            #pragma unroll
            for (int nt = 0; nt < 4; nt++) {
                int nb = n_warp + nt * 8;
                bf[nt][0] = uB[(nb + ar)*TPAD + k0 + ac];
                bf[nt][1] = uB[(nb + ar)*TPAD + k0 + ac + 4];
            }
            #pragma unroll
            for (int mt = 0; mt < 4; mt++)
                #pragma unroll
                for (int nt = 0; nt < 4; nt++)
                    mma_tf32(c[mt][nt], af[mt], bf[nt]);
        }
        __syncthreads();
    }

    int cr = lane >> 2, cc = (lane & 3) * 2;
    #pragma unroll
    for (int mt = 0; mt < 4; mt++) {
        size_t r0 = (size_t)(bm + m_warp + mt * 16 + cr);
        #pragma unroll
        for (int nt = 0; nt < 4; nt++) {
            int col = bn + n_warp + nt * 8 + cc;
            if (col < N) {
                float v0 = c[mt][nt][0], v1 = c[mt][nt][1];
                float v2 = c[mt][nt][2], v3 = c[mt][nt][3];
                if (GELU) {
                    float b0v = bias[col], b1v = bias[col + 1];
                    v0 += b0v; v1 += b1v; v2 += b0v; v3 += b1v;
                    v0 = 0.5f * v0 * (1.0f + erff(v0 * 0.70710678118654752f));
                    v1 = 0.5f * v1 * (1.0f + erff(v1 * 0.70710678118654752f));
                    v2 = 0.5f * v2 * (1.0f + erff(v2 * 0.70710678118654752f));
                    v3 = 0.5f * v3 * (1.0f + erff(v3 * 0.70710678118654752f));
                }
                *reinterpret_cast<float2*>(C + r0 * N + col) = make_float2(v0, v1);
                *reinterpret_cast<float2*>(C + (r0 + 8) * N + col) = make_float2(v2, v3);
            }
        }
    }
}

// ---------------- beta = sigmoid(hs @ Wb^T) ----------------
__global__ __launch_bounds__(128) void beta_kernel(const float* __restrict__ hs,
                                                   const float* __restrict__ Wb)
{
    int row = blockIdx.x;
    int w = threadIdx.x >> 5, lane = threadIdx.x & 31;
    const float* xr = hs + (size_t)row * DD;
    const float* wr = Wb + (size_t)w * DD;
    float acc = 0.f;
    for (int d = lane; d < DD; d += 32) acc += xr[d] * wr[d];
    acc = wred_sum(acc);
    if (lane == 0) g_beta[row * HH + w] = 1.f / (1.f + __expf(-acc));
}

// ---------------- depthwise causal conv K=4 + silu for v only (float4) ----------------
__global__ __launch_bounds__(256) void dwconv_v_kernel(
    const float* __restrict__ x, const float* __restrict__ w, float* __restrict__ y)
{
    int idx = blockIdx.x * 256 + threadIdx.x;
    int c = (idx & 255) * 4;
    int row = idx >> 8;
    int l = row & (LL - 1);
    float4 wv0 = *reinterpret_cast<const float4*>(&w[(c+0)*4]);
    float4 wv1 = *reinterpret_cast<const float4*>(&w[(c+1)*4]);
    float4 wv2 = *reinterpret_cast<const float4*>(&w[(c+2)*4]);
    float4 wv3 = *reinterpret_cast<const float4*>(&w[(c+3)*4]);
    const float* pw0 = &wv0.x; const float* pw1 = &wv1.x;
    const float* pw2 = &wv2.x; const float* pw3 = &wv3.x;
    float4 acc = make_float4(0.f,0.f,0.f,0.f);
    #pragma unroll
    for (int j = 0; j < 4; j++) {
        int ll = l - 3 + j;
        if (ll >= 0) {
            float4 xv = *reinterpret_cast<const float4*>(&x[(size_t)(row - 3 + j) * DD + c]);
            acc.x = fmaf(xv.x, pw0[j], acc.x);
            acc.y = fmaf(xv.y, pw1[j], acc.y);
            acc.z = fmaf(xv.z, pw2[j], acc.z);
            acc.w = fmaf(xv.w, pw3[j], acc.w);
        }
    }
    acc.x = acc.x / (1.f + __expf(-acc.x));
    acc.y = acc.y / (1.f + __expf(-acc.y));
    acc.z = acc.z / (1.f + __expf(-acc.z));
    acc.w = acc.w / (1.f + __expf(-acc.w));
    *reinterpret_cast<float4*>(&y[(size_t)row * DD + c]) = acc;
}

// ---------------- delta stage A: fused q/k dwconv+silu, 2-row blocking + d-split ----------------
#define PADA 260
#define SA_QS 0
#define SA_KS (32*PADA)
#define SA_AT (64*PADA)
#define SA_BE (64*PADA + 1056)
#define SA_RN (64*PADA + 1088)
#define SA_SC (64*PADA + 1152)
#define SA_FLOATS (64*PADA + 1152 + 1024)
__global__ __launch_bounds__(256) void stageA_kernel(const float* __restrict__ wq_conv,
                                                     const float* __restrict__ wk_conv)
{
    extern __shared__ float sm[];
    float* q_s  = sm + SA_QS;
    float* k_s  = sm + SA_KS;
    float* attn = sm + SA_AT;
    float* be_s = sm + SA_BE;
    float* rn_s = sm + SA_RN;
    float* sc_s = sm + SA_SC;

    int t = threadIdx.x;
    int ci = blockIdx.x, h = blockIdx.y, b = blockIdx.z;
    size_t rowbase = (size_t)b * LL + (size_t)ci * 32;
    size_t col0 = (size_t)h * DV;

    int dhalf = t >> 7;
    int tt = t & 127;
    int i0 = tt >> 3;
    int jg = tt & 7;
    int dbase = dhalf * 128;

    // fused causal conv K=4 + silu for q,k (replaces dwconv kernel for q/k)
    {
        int cg = (int)col0 + t;
        float qw0 = wq_conv[cg*4+0], qw1 = wq_conv[cg*4+1];
        float qw2 = wq_conv[cg*4+2], qw3 = wq_conv[cg*4+3];
        float kw0 = wk_conv[cg*4+0], kw1 = wk_conv[cg*4+1];
        float kw2 = wk_conv[cg*4+2], kw3 = wk_conv[cg*4+3];
        int l0 = ci * 32;
        float xq0=0.f, xq1=0.f, xq2=0.f, xk0=0.f, xk1=0.f, xk2=0.f;
        #pragma unroll
        for (int j = 0; j < 3; j++) {
            float vq = 0.f, vk = 0.f;
            if (l0 - 3 + j >= 0) {
                vq = g_qlin[(rowbase - 3 + j) * DD + cg];
                vk = g_klin[(rowbase - 3 + j) * DD + cg];
            }
            xq0 = xq1; xq1 = xq2; xq2 = vq;
            xk0 = xk1; xk1 = xk2; xk2 = vk;
        }
        #pragma unroll 4
        for (int i = 0; i < 32; i++) {
            float vq = g_qlin[(rowbase + i) * DD + cg];
            float vk = g_klin[(rowbase + i) * DD + cg];
            float aq = 0.f, ak = 0.f;
            aq = fmaf(xq0, qw0, aq); aq = fmaf(xq1, qw1, aq);
            aq = fmaf(xq2, qw2, aq); aq = fmaf(vq,  qw3, aq);
            ak = fmaf(xk0, kw0, ak); ak = fmaf(xk1, kw1, ak);
            ak = fmaf(xk2, kw2, ak); ak = fmaf(vk,  kw3, ak);
            aq = aq / (1.f + __expf(-aq));
            ak = ak / (1.f + __expf(-ak));
            q_s[i*PADA + t] = aq;
            k_s[i*PADA + t] = ak;
            xq0 = xq1; xq1 = xq2; xq2 = vq;
            xk0 = xk1; xk1 = xk2; xk2 = vk;
        }
    }
    if (t < 32) be_s[t] = g_beta[(rowbase + t) * HH + h];
    __syncthreads();

    {
        int r = t >> 3, g = t & 7;
        float sq = 0.f, sk = 0.f;
        #pragma unroll
        for (int dd = 0; dd < 32; dd++) {
            float a = q_s[r*PADA + g + 8*dd]; sq += a*a;
            float c2 = k_s[r*PADA + g + 8*dd]; sk += c2*c2;
        }
        #pragma unroll
        for (int o = 4; o > 0; o >>= 1) {
            sq += __shfl_xor_sync(0xffffffffu, sq, o);
            sk += __shfl_xor_sync(0xffffffffu, sk, o);
        }
        if (g == 0) { rn_s[r] = rsqrtf(sq + 1e-12f); rn_s[32+r] = rsqrtf(sk + 1e-12f); }
    }
    __syncthreads();
    #pragma unroll
    for (int e = 0; e < 8; e++) {
        int idx = e*256 + t;
        int i = idx >> 6, c = (idx & 63) * 4;
        float rq = rn_s[i], rk = rn_s[32+i];
        float4 qv = *reinterpret_cast<float4*>(&q_s[i*PADA + c]);
        qv.x *= rq; qv.y *= rq; qv.z *= rq; qv.w *= rq;
        *reinterpret_cast<float4*>(&q_s[i*PADA + c]) = qv;
        float4 kv = *reinterpret_cast<float4*>(&k_s[i*PADA + c]);
        kv.x *= rk; kv.y *= rk; kv.z *= rk; kv.w *= rk;
        *reinterpret_cast<float4*>(&k_s[i*PADA + c]) = kv;
    }
    __syncthreads();

    size_t chbase = (((size_t)b * HH + h) * NC + ci) * (32 * DV);
    size_t labase = (((size_t)b * HH + h) * NC + ci) * 1024;

    {
        float acc0[4] = {0.f,0.f,0.f,0.f};
        float acc1[4] = {0.f,0.f,0.f,0.f};
        for (int d = 0; d < 128; d += 4) {
            float4 q0 = *reinterpret_cast<const float4*>(&q_s[i0*PADA + dbase + d]);
            float4 q1 = *reinterpret_cast<const float4*>(&q_s[(i0+16)*PADA + dbase + d]);
            #pragma unroll
            for (int jj = 0; jj < 4; jj++) {
                float4 kv = *reinterpret_cast<const float4*>(&k_s[(jg + 8*jj)*PADA + dbase + d]);
                acc0[jj] = fmaf(q0.x, kv.x, acc0[jj]);
                acc0[jj] = fmaf(q0.y, kv.y, acc0[jj]);
                acc0[jj] = fmaf(q0.z, kv.z, acc0[jj]);
                acc0[jj] = fmaf(q0.w, kv.w, acc0[jj]);
                acc1[jj] = fmaf(q1.x, kv.x, acc1[jj]);
                acc1[jj] = fmaf(q1.y, kv.y, acc1[jj]);
                acc1[jj] = fmaf(q1.z, kv.z, acc1[jj]);
                acc1[jj] = fmaf(q1.w, kv.w, acc1[jj]);
            }
        }
        if (dhalf == 1) {
            #pragma unroll
            for (int jj = 0; jj < 4; jj++) {
                sc_s[tt*8 + jj]     = acc0[jj];
                sc_s[tt*8 + 4 + jj] = acc1[jj];
            }
        }
        __syncthreads();
        if (dhalf == 0) {
            #pragma unroll
            for (int jj = 0; jj < 4; jj++) {
                float v0 = acc0[jj] + sc_s[tt*8 + jj];
                float v1 = acc1[jj] + sc_s[tt*8 + 4 + jj];
                int j = jg + 8*jj;
                g_la[labase + i0*32 + j]      = (j <= i0)      ? v0 : 0.f;
                g_la[labase + (i0+16)*32 + j] = (j <= i0 + 16) ? v1 : 0.f;
            }
        }
    }
    __syncthreads();

    #pragma unroll
    for (int e = 0; e < 8; e++) {
        int idx = e*256 + t;
        int i = idx >> 6, c = (idx & 63) * 4;
        *reinterpret_cast<float4*>(&g_qn[chbase + i*DV + c]) =
            *reinterpret_cast<const float4*>(&q_s[i*PADA + c]);
        *reinterpret_cast<float4*>(&g_kn[chbase + i*DV + c]) =
            *reinterpret_cast<const float4*>(&k_s[i*PADA + c]);
        float4 vv = *reinterpret_cast<const float4*>(&g_v[(rowbase+i)*DD + col0 + c]);
        float be = be_s[i];
        vv.x *= be; vv.y *= be; vv.z *= be; vv.w *= be;
        *reinterpret_cast<float4*>(&q_s[i*PADA + c]) = vv;
    }
    __syncthreads();

    {
        float bi0 = be_s[i0], bi1 = be_s[i0 + 16];
        float acc0[4] = {0.f,0.f,0.f,0.f};
        float acc1[4] = {0.f,0.f,0.f,0.f};
        for (int d = 0; d < 128; d += 4) {
            float4 k0v = *reinterpret_cast<const float4*>(&k_s[i0*PADA + dbase + d]);
            k0v.x *= bi0; k0v.y *= bi0; k0v.z *= bi0; k0v.w *= bi0;
            float4 k1v = *reinterpret_cast<const float4*>(&k_s[(i0+16)*PADA + dbase + d]);
            k1v.x *= bi1; k1v.y *= bi1; k1v.z *= bi1; k1v.w *= bi1;
            #pragma unroll
            for (int jj = 0; jj < 4; jj++) {
                float4 kv = *reinterpret_cast<const float4*>(&k_s[(jg + 8*jj)*PADA + dbase + d]);
                acc0[jj] = fmaf(k0v.x, kv.x, acc0[jj]);
                acc0[jj] = fmaf(k0v.y, kv.y, acc0[jj]);
                acc0[jj] = fmaf(k0v.z, kv.z, acc0[jj]);
                acc0[jj] = fmaf(k0v.w, kv.w, acc0[jj]);
                acc1[jj] = fmaf(k1v.x, kv.x, acc1[jj]);
                acc1[jj] = fmaf(k1v.y, kv.y, acc1[jj]);
                acc1[jj] = fmaf(k1v.z, kv.z, acc1[jj]);
                acc1[jj] = fmaf(k1v.w, kv.w, acc1[jj]);
            }
        }
        if (dhalf == 1) {
            #pragma unroll
            for (int jj = 0; jj < 4; jj++) {
                sc_s[tt*8 + jj]     = acc0[jj];
                sc_s[tt*8 + 4 + jj] = acc1[jj];
            }
        }
        __syncthreads();
        if (dhalf == 0) {
            #pragma unroll
            for (int jj = 0; jj < 4; jj++) {
                float v0 = acc0[jj] + sc_s[tt*8 + jj];
                float v1 = acc1[jj] + sc_s[tt*8 + 4 + jj];
                int j = jg + 8*jj;
                attn[i0*33 + j]      = (i0 > j)      ? -v0 : 0.f;
                attn[(i0+16)*33 + j] = (i0 + 16 > j) ? -v1 : 0.f;
            }
        }
    }
    __syncthreads();

    if (t < 32) {
        int j = t;
        for (int i = 1; i < 32; i++) {
            float upd = 0.f;
            if (j < i)
                for (int k = j + 1; k < i; k++) upd += attn[i*33 + k] * attn[k*33 + j];
            __syncwarp();
            if (j < i) attn[i*33 + j] += upd;
            __syncwarp();
        }
        attn[j*33 + j] = 1.f;
    }
    __syncthreads();

    {
        int i = t >> 3, g = t & 7;
        float2 accu[16];
        #pragma unroll
        for (int dd = 0; dd < 16; dd++) accu[dd] = make_float2(0.f, 0.f);
        for (int k = 0; k < 32; k++) {
            float av = attn[i*33 + k];
            #pragma unroll
            for (int dd = 0; dd < 16; dd++) {
                float2 qv = *reinterpret_cast<const float2*>(&q_s[k*PADA + g*2 + dd*16]);
                accu[dd].x = fmaf(av, qv.x, accu[dd].x);
                accu[dd].y = fmaf(av, qv.y, accu[dd].y);
            }
        }
        #pragma unroll
        for (int dd = 0; dd < 16; dd++)
            *reinterpret_cast<float2*>(&g_u[chbase + i*DV + g*2 + dd*16]) = accu[dd];

        #pragma unroll
        for (int dd = 0; dd < 16; dd++) accu[dd] = make_float2(0.f, 0.f);
        for (int k = 0; k < 32; k++) {
            float av = attn[i*33 + k] * be_s[k];
            #pragma unroll
            for (int dd = 0; dd < 16; dd++) {
                float2 kv = *reinterpret_cast<const float2*>(&k_s[k*PADA + g*2 + dd*16]);
                accu[dd].x = fmaf(av, kv.x, accu[dd].x);
                accu[dd].y = fmaf(av, kv.y, accu[dd].y);
            }
        }
        #pragma unroll
        for (int dd = 0; dd < 16; dd++)
            *reinterpret_cast<float2*>(&g_w[chbase + i*DV + g*2 + dd*16]) = accu[dd];
    }
}

// ---------------- delta stage B + fused FIR/copy (512 threads) ----------------
#define SBW 264
#define SB2_W   0
#define SB2_Q   8448
#define SB2_K   16896
#define SB2_LA  25344
#define SB2_BUF 26368
#define SB2_S   52736
#define SB2_UI  57344
#define SB2_FLOATS 57856
#define BAR_SCAN() asm volatile("bar.sync 1, 256;" ::: "memory")

__global__ __launch_bounds__(512) void stageB_kernel(
    const float* __restrict__ w3, const float* __restrict__ w7,
    const float* __restrict__ w25, const float* __restrict__ w1,
    const float* __restrict__ hs)
{
    extern __shared__ float sm[];
    int t = threadIdx.x;
    int js = blockIdx.x, h = blockIdx.y, b = blockIdx.z;

    if (t >= 256) {
        int lt = t - 256;
        int blockLin = js + 16 * h + 64 * b;
        int rbase = blockLin * 64;

        for (int r = 0; r < 64; r++) {
            int row = rbase + r;
            *reinterpret_cast<float4*>(&g_rin[(size_t)row * RIN + lt*4]) =
                *reinterpret_cast<const float4*>(&hs[(size_t)row * DD + lt*4]);
        }

        for (int cho = 0; cho < 4; cho++) {
            int c = cho * 256 + lt;
            float fw3[3], fw7[7], fw25[25], fw1;
            #pragma unroll
            for (int j = 0; j < 3; j++)  fw3[j]  = w3[c*3 + j];
            #pragma unroll
            for (int j = 0; j < 7; j++)  fw7[j]  = w7[c*7 + j];
            #pragma unroll
            for (int j = 0; j < 25; j++) fw25[j] = w25[c*25 + j];
            fw1 = w1[c];
            for (int r = 0; r < 64; r++) {
                int row = rbase + r;
                int l = row & (LL - 1);
                float x[25];
                #pragma unroll
                for (int tt = 0; tt < 25; tt++)
                    x[tt] = (l - tt >= 0) ? g_v[(size_t)(row - tt) * DD + c] : 0.f;
                float a3 = 0.f, a7 = 0.f, a25 = 0.f;
                #pragma unroll
                for (int j = 0; j < 3; j++)  a3  += fw3[j]  * x[2  - j];
                #pragma unroll
                for (int j = 0; j < 7; j++)  a7  += fw7[j]  * x[6  - j];
                #pragma unroll
                for (int j = 0; j < 25; j++) a25 += fw25[j] * x[24 - j];
                size_t oi = (size_t)row * DD + c;
                g_br0[oi] = a3;
                g_br1[oi] = a7;
                g_br2[oi] = a25;
                g_br4[oi] = fw1 * x[0];
            }
        }
        return;
    }

    float* S  = sm + SB2_S;
    float* ui = sm + SB2_UI;

    #pragma unroll
    for (int j = 0; j < 16; j++) S[t*18 + j] = 0.f;
    size_t bh = (size_t)b * HH + h;
    int ii = t >> 3, jc = t & 7;

    auto issue_chunk = [&](int ci) {
        float* buf = sm + (ci & 1) * SB2_BUF;
        size_t chb = (bh * NC + ci) * (32 * DV);
        #pragma unroll
        for (int e = 0; e < 8; e++) {
            int idx = e * 256 + t;
            int i = idx >> 6, cc = idx & 63;
            int goff = idx * 4;
            int soff = i * SBW + cc * 4;
            cp_async16(smem_u32(&buf[SB2_W + soff]), g_w  + chb + goff, 16);
            cp_async16(smem_u32(&buf[SB2_Q + soff]), g_qn + chb + goff, 16);
            cp_async16(smem_u32(&buf[SB2_K + soff]), g_kn + chb + goff, 16);
        }
        cp_async16(smem_u32(&buf[SB2_LA + t*4]), g_la + (bh * NC + ci) * 1024 + t*4, 16);
        asm volatile("cp.async.commit_group;");
    };

    issue_chunk(0);
    issue_chunk(1);
    float2 uv = *reinterpret_cast<const float2*>(
        &g_u[(bh * NC + 0) * (32 * DV) + (size_t)ii * DV + js*16 + 2*jc]);

    for (int ci = 0; ci < NC; ci++) {
        asm volatile("cp.async.wait_group %0;" :: "n"(1));
        BAR_SCAN();
        float* buf  = sm + (ci & 1) * SB2_BUF;
        float* w_s  = buf + SB2_W;
        float* q_s  = buf + SB2_Q;
        float* k_s  = buf + SB2_K;
        float* la_s = buf + SB2_LA;

        float2 uv_next = make_float2(0.f, 0.f);
        if (ci + 1 < NC)
            uv_next = *reinterpret_cast<const float2*>(
                &g_u[(bh * NC + ci + 1) * (32 * DV) + (size_t)ii * DV + js*16 + 2*jc]);

        float a0 = uv.x, a1 = uv.y, o0 = 0.f, o1 = 0.f;
        #pragma unroll 4
        for (int m = 0; m < 256; m += 2) {
            float2 wv = *reinterpret_cast<const float2*>(&w_s[ii*SBW + m]);
            float2 qv = *reinterpret_cast<const float2*>(&q_s[ii*SBW + m]);
            float2 s0 = *reinterpret_cast<const float2*>(&S[m*18 + 2*jc]);
            float2 s1 = *reinterpret_cast<const float2*>(&S[(m+1)*18 + 2*jc]);
            a0 = fmaf(-wv.x, s0.x, a0); a1 = fmaf(-wv.x, s0.y, a1);
            o0 = fmaf( qv.x, s0.x, o0); o1 = fmaf( qv.x, s0.y, o1);
            a0 = fmaf(-wv.y, s1.x, a0); a1 = fmaf(-wv.y, s1.y, a1);
            o0 = fmaf( qv.y, s1.x, o0); o1 = fmaf( qv.y, s1.y, o1);
        }
        ui[ii*16 + 2*jc]     = a0;
        ui[ii*16 + 2*jc + 1] = a1;
        BAR_SCAN();

        #pragma unroll
        for (int k = 0; k < 32; k++) {
            float lv = la_s[ii*32 + k];
            float2 uu = *reinterpret_cast<const float2*>(&ui[k*16 + 2*jc]);
            o0 = fmaf(lv, uu.x, o0); o1 = fmaf(lv, uu.y, o1);
        }
        size_t orow = ((size_t)b * LL + (size_t)ci*32 + ii) * DD + (size_t)h * DV + js*16 + 2*jc;
        *reinterpret_cast<float2*>(&g_br3[orow]) = make_float2(o0, o1);

        float acc[16];
        #pragma unroll
        for (int j = 0; j < 16; j++) acc[j] = 0.f;
        #pragma unroll 4
        for (int i = 0; i < 32; i++) {
            float kv = k_s[i*SBW + t];
            const float4* up = reinterpret_cast<const float4*>(&ui[i*16]);
            float4 u0 = up[0], u1 = up[1], u2 = up[2], u3 = up[3];
            acc[0]  = fmaf(kv, u0.x, acc[0]);  acc[1]  = fmaf(kv, u0.y, acc[1]);
            acc[2]  = fmaf(kv, u0.z, acc[2]);  acc[3]  = fmaf(kv, u0.w, acc[3]);
            acc[4]  = fmaf(kv, u1.x, acc[4]);  acc[5]  = fmaf(kv, u1.y, acc[5]);
            acc[6]  = fmaf(kv, u1.z, acc[6]);  acc[7]  = fmaf(kv, u1.w, acc[7]);
            acc[8]  = fmaf(kv, u2.x, acc[8]);  acc[9]  = fmaf(kv, u2.y, acc[9]);
            acc[10] = fmaf(kv, u2.z, acc[10]); acc[11] = fmaf(kv, u2.w, acc[11]);
            acc[12] = fmaf(kv, u3.x, acc[12]); acc[13] = fmaf(kv, u3.y, acc[13]);
            acc[14] = fmaf(kv, u3.z, acc[14]); acc[15] = fmaf(kv, u3.w, acc[15]);
        }
        #pragma unroll
        for (int j = 0; j < 16; j++) S[t*18 + j] += acc[j];

        BAR_SCAN();
        if (ci + 2 < NC) issue_chunk(ci + 2);
        else asm volatile("cp.async.commit_group;");
        uv = uv_next;
    }
}

// ---------------- branch stats (float4 loads) ----------------
__global__ __launch_bounds__(256) void stats_kernel()
{
    int gw = blockIdx.x * 8 + (threadIdx.x >> 5);
    int lane = threadIdx.x & 31;
    int row = gw >> 2, h = gw & 3;
    size_t base = (size_t)row * DD + (size_t)h * DV + lane * 8;
    float x[5][8];
    #pragma unroll
    for (int p = 0; p < 5; p++) {
        const float* bp = branch_ptr(p);
        float4 a = *reinterpret_cast<const float4*>(&bp[base]);
        float4 bq = *reinterpret_cast<const float4*>(&bp[base + 4]);
        x[p][0]=a.x; x[p][1]=a.y; x[p][2]=a.z; x[p][3]=a.w;
        x[p][4]=bq.x; x[p][5]=bq.y; x[p][6]=bq.z; x[p][7]=bq.w;
    }
    float ssv[5];
    float* rout = g_rin + (size_t)row * RIN;
    #pragma unroll
    for (int p = 0; p < 5; p++) {
        float s = 0.f, ss = 0.f, mx = -1e30f;
        #pragma unroll
        for (int e = 0; e < 8; e++) {
            float v = x[p][e];
            s += v; ss += v*v; mx = fmaxf(mx, v);
        }
        s = wred_sum(s); ss = wred_sum(ss); mx = wred_max(mx);
        float ez[8]; float Zp = 0.f;
        #pragma unroll
        for (int e = 0; e < 8; e++) { ez[e] = __expf(x[p][e] - mx); Zp += ez[e]; }
        float Z = wred_sum(Zp);
        float ep = 0.f;
        #pragma unroll
        for (int e = 0; e < 8; e++) { float smv = ez[e] / Z; ep += smv * __logf(smv + 1e-8f); }
        float ent = -wred_sum(ep);
        ssv[p] = ss;
        if (lane == 0) {
            rout[1024 + (p*4 + 0)*HH + h] = s * (1.f/256.f);
            rout[1024 + (p*4 + 1)*HH + h] = (ss - s*s*(1.f/256.f)) * (1.f/255.f);
            rout[1024 + (p*4 + 2)*HH + h] = mx;
            rout[1024 + (p*4 + 3)*HH + h] = ent;
        }
    }
    int c = 0;
    #pragma unroll
    for (int i = 0; i < 5; i++)
        #pragma unroll
        for (int j = i + 1; j < 5; j++) {
            float d = 0.f;
            #pragma unroll
            for (int e = 0; e < 8; e++) d += x[i][e] * x[j][e];
            d = wred_sum(d);
            if (lane == 0)
                rout[1104 + c*HH + h] = d / (sqrtf(ssv[i]) * sqrtf(ssv[j]) + 1e-8f);
            c++;
        }
}

// ---------------- logits + softmax floor + mix + RMSnorm : 8 rows per block ----------------
#define LMR 8
#define HPAD 2292
#define LM_SMEM (LMR*HPAD*4)
__global__ __launch_bounds__(256) void logits_mix_kernel(const float* __restrict__ W2,
                                                         const float* __restrict__ b2,
                                                         const float* __restrict__ norm_w)
{
    extern __shared__ float lsm[];
    __shared__ float lg_s[LMR][20];
    __shared__ float pr_s[LMR][20];
    __shared__ float wred_s[LMR][8];
    int t = threadIdx.x;
    int wid = t >> 5, lane = t & 31;
    int row0 = blockIdx.x * LMR;

    for (int idx = t; idx < LMR * 572; idx += 256) {
        int r = idx / 572, c4 = idx % 572;
        *reinterpret_cast<float4*>(&lsm[r*HPAD + c4*4]) =
            *reinterpret_cast<const float4*>(&g_hrt[(size_t)(row0 + r) * RH + c4*4]);
    }
    __syncthreads();

    {
        const float* hr = &lsm[wid*HPAD];
        for (int n = 0; n < 20; n++) {
            const float* w2r = W2 + (size_t)n * RH;
            float acc = 0.f;
            for (int idx = lane; idx < 572; idx += 32) {
                float4 hv = *reinterpret_cast<const float4*>(&hr[idx*4]);
                float4 wv = *reinterpret_cast<const float4*>(&w2r[idx*4]);
                acc += hv.x*wv.x + hv.y*wv.y + hv.z*wv.z + hv.w*wv.w;
            }
            acc = wred_sum(acc);
            if (lane == 0) lg_s[wid][n] = acc + b2[n];
        }
    }
    __syncthreads();
    if (t < 32) {
        int r = t >> 2, hh = t & 3;
        float m = -1e30f;
        #pragma unroll
        for (int p = 0; p < 5; p++) m = fmaxf(m, lg_s[r][hh*5 + p]);
        float Z = 0.f, e[5];
        #pragma unroll
        for (int p = 0; p < 5; p++) { e[p] = __expf(lg_s[r][hh*5 + p] - m); Z += e[p]; }
        #pragma unroll
        for (int p = 0; p < 5; p++) pr_s[r][hh*5 + p] = e[p] / Z * 0.95f + 0.01f;
    }
    __syncthreads();

    int c = t * 4;
    int hh = t >> 6;
    float4 nw4 = *reinterpret_cast<const float4*>(&norm_w[c & 255]);
    float4 val[LMR];
    #pragma unroll
    for (int r = 0; r < LMR; r++) {
        size_t base = (size_t)(row0 + r) * DD + c;
        float4 acc = make_float4(0.f,0.f,0.f,0.f);
        #pragma unroll
        for (int p = 0; p < 5; p++) {
            float4 bv = *reinterpret_cast<const float4*>(&branch_ptr(p)[base]);
            float pr = pr_s[r][hh*5 + p];
            acc.x = fmaf(pr, bv.x, acc.x);
            acc.y = fmaf(pr, bv.y, acc.y);
            acc.z = fmaf(pr, bv.z, acc.z);
            acc.w = fmaf(pr, bv.w, acc.w);
        }
        val[r] = acc;
        float sq = acc.x*acc.x + acc.y*acc.y + acc.z*acc.z + acc.w*acc.w;
        sq = wred_sum(sq);
        if (lane == 0) wred_s[r][wid] = sq;
    }
    __syncthreads();
    #pragma unroll
    for (int r = 0; r < LMR; r++) {
        float s = wred_s[r][hh*2] + wred_s[r][hh*2 + 1];
        float rms = rsqrtf(s * (1.f/256.f) + 1e-5f);
        float4 v = val[r];
        v.x *= rms * nw4.x; v.y *= rms * nw4.y;
        v.z *= rms * nw4.z; v.w *= rms * nw4.w;
        *reinterpret_cast<float4*>(&g_mix[(size_t)(row0 + r) * DD + c]) = v;
    }
}

// ---------------- launch ----------------
static float* sym(const void* s) { void* p = nullptr; cudaGetSymbolAddress(&p, s); return (float*)p; }

extern "C" void kernel_launch(void* const* d_in, const int* in_sizes, int n_in,
                              void* d_out, int out_size)
{
    const float* hs       = (const float*)d_in[0];
    const float* Wq       = (const float*)d_in[1];
    const float* Wk       = (const float*)d_in[2];
    const float* Wv       = (const float*)d_in[3];
    const float* wq_conv  = (const float*)d_in[4];
    const float* wk_conv  = (const float*)d_in[5];
    const float* wv_conv  = (const float*)d_in[6];
    const float* Wb       = (const float*)d_in[7];
    const float* fir_s_w  = (const float*)d_in[8];
    const float* fir_m_w  = (const float*)d_in[9];
    const float* fir_l_w  = (const float*)d_in[10];
    const float* fir_id_w = (const float*)d_in[11];
    const float* W1       = (const float*)d_in[12];
    const float* b1       = (const float*)d_in[13];
    const float* W2       = (const float*)d_in[14];
    const float* b2       = (const float*)d_in[15];
    const float* norm_w   = (const float*)d_in[16];
    const float* Wo       = (const float*)d_in[17];
    float* out = (float*)d_out;

    float* p_qlin = sym(g_qlin); float* p_klin = sym(g_klin); float* p_vlin = sym(g_vlin);
    float* p_v = sym(g_v);
    float* p_rin = sym(g_rin); float* p_hrt = sym(g_hrt); float* p_mix = sym(g_mix);

    cudaFuncSetAttribute(tf32gemm_kernel<false>, cudaFuncAttributeMaxDynamicSharedMemorySize, GEMM_SMEM);
    cudaFuncSetAttribute(tf32gemm_kernel<true>, cudaFuncAttributeMaxDynamicSharedMemorySize, GEMM_SMEM);
    cudaFuncSetAttribute(stageA_kernel, cudaFuncAttributeMaxDynamicSharedMemorySize, SA_FLOATS*4);
    cudaFuncSetAttribute(stageB_kernel, cudaFuncAttributeMaxDynamicSharedMemorySize, SB2_FLOATS*4);
    cudaFuncSetAttribute(logits_mix_kernel, cudaFuncAttributeMaxDynamicSharedMemorySize, LM_SMEM);

    beta_kernel<<<BLROWS, 128>>>(hs, Wb);
    tf32gemm_kernel<false><<<dim3(DD/TBN, BLROWS/TBM, 3), 256, GEMM_SMEM>>>(
        hs, Wq, Wk, Wv, nullptr, p_qlin, p_klin, p_vlin, BLROWS, DD, DD);

    int cg4 = BLROWS*DD/1024;
    dwconv_v_kernel<<<cg4, 256>>>(p_vlin, wv_conv, p_v);

    stageA_kernel<<<dim3(NC, HH, BB), 256, SA_FLOATS*4>>>(wq_conv, wk_conv);
    stageB_kernel<<<dim3(16, HH, BB), 512, SB2_FLOATS*4>>>(
        fir_s_w, fir_m_w, fir_l_w, fir_id_w, hs);

    stats_kernel<<<BLROWS*HH/8, 256>>>();

    tf32gemm_kernel<true><<<dim3((RH+TBN-1)/TBN, BLROWS/TBM, 1), 256, GEMM_SMEM>>>(
        p_rin, W1, W1, W1, b1, p_hrt, p_hrt, p_hrt, BLROWS, RH, RIN);
    logits_mix_kernel<<<BLROWS/LMR, 256, LM_SMEM>>>(W2, b2, norm_w);
    tf32gemm_kernel<false><<<dim3(DD/TBN, BLROWS/TBM, 1), 256, GEMM_SMEM>>>(
        p_mix, Wo, Wo, Wo, nullptr, out, out, out, BLROWS, DD, DD);
}

// round 16
// speedup vs baseline: 1.0434x; 1.0259x over previous
#include <cuda_runtime.h>
#include <cuda_bf16.h>
#include <math.h>
#include <stdint.h>

#define BB 2
#define LL 4096
#define DD 1024
#define HH 4
#define DV 256
#define NP 5
#define NC 128
#define BLROWS (BB*LL)
#define RIN 1144
#define RH 2288

// ---------------- scratch ----------------
__device__ float g_qlin[BLROWS*DD];
__device__ float g_klin[BLROWS*DD];
__device__ float g_vlin[BLROWS*DD];
__device__ float g_v[BLROWS*DD];
__device__ float g_beta[BLROWS*HH];
__device__ float g_qn[BLROWS*DD];
__device__ float g_kn[BLROWS*DD];
__device__ float g_u[BLROWS*DD];
__device__ float g_w[BLROWS*DD];
__device__ float g_la[BB*HH*NC*32*32];
__device__ float g_br0[BLROWS*DD];
__device__ float g_br1[BLROWS*DD];
__device__ float g_br2[BLROWS*DD];
__device__ float g_br3[BLROWS*DD];
__device__ float g_br4[BLROWS*DD];
__device__ float g_rin[BLROWS*RIN];
__device__ float g_hrt[BLROWS*RH];
__device__ float g_mix[BLROWS*DD];

__device__ __forceinline__ const float* branch_ptr(int p) {
    switch (p) {
        case 0: return g_br0;
        case 1: return g_br1;
        case 2: return g_br2;
        case 3: return g_br3;
        default: return g_br4;
    }
}
__device__ __forceinline__ float wred_sum(float v) {
    #pragma unroll
    for (int o = 16; o > 0; o >>= 1) v += __shfl_xor_sync(0xffffffffu, v, o);
    return v;
}
__device__ __forceinline__ float wred_max(float v) {
    #pragma unroll
    for (int o = 16; o > 0; o >>= 1) v = fmaxf(v, __shfl_xor_sync(0xffffffffu, v, o));
    return v;
}
__device__ __forceinline__ void mma_tf32(float c[4], const uint32_t a[4], const uint32_t b[2]) {
    asm volatile("mma.sync.aligned.m16n8k8.row.col.f32.tf32.tf32.f32 "
        "{%0,%1,%2,%3}, {%4,%5,%6,%7}, {%8,%9}, {%0,%1,%2,%3};\n"
        : "+f"(c[0]), "+f"(c[1]), "+f"(c[2]), "+f"(c[3])
        : "r"(a[0]), "r"(a[1]), "r"(a[2]), "r"(a[3]), "r"(b[0]), "r"(b[1]));
}
__device__ __forceinline__ uint32_t smem_u32(const void* p) {
    return (uint32_t)__cvta_generic_to_shared(p);
}
__device__ __forceinline__ void cp_async16(uint32_t dst, const void* src, int src_bytes) {
    asm volatile("cp.async.cg.shared.global [%0], [%1], 16, %2;"
                 :: "r"(dst), "l"(src), "r"(src_bytes));
}

// ---------------- TF32 tensor GEMM: TBK=32, 2 stages, raw f32 bits ----------------
#define TBM 128
#define TBN 128
#define TBK 32
#define TPAD 36
#define GEMM_SMEM (2*TBM*TPAD*2*4)

template<bool GELU>
__global__ __launch_bounds__(256) void tf32gemm_kernel(
    const float* __restrict__ A,
    const float* __restrict__ B0, const float* __restrict__ B1, const float* __restrict__ B2,
    const float* __restrict__ bias,
    float* __restrict__ C0, float* __restrict__ C1, float* __restrict__ C2,
    int M, int N, int K)
{
    const float* Bw = (blockIdx.z == 0) ? B0 : ((blockIdx.z == 1) ? B1 : B2);
    float* C       = (blockIdx.z == 0) ? C0 : ((blockIdx.z == 1) ? C1 : C2);

    extern __shared__ float gsm[];
    float* As = gsm;
    float* Bs = gsm + 2*TBM*TPAD;
    int tid = threadIdx.x;
    int wid = tid >> 5, lane = tid & 31;
    int m_warp = (wid >> 2) * 64;
    int n_warp = (wid & 3) * 32;
    int bm = blockIdx.y * TBM, bn = blockIdx.x * TBN;

    float c[4][4][4];
    #pragma unroll
    for (int mt = 0; mt < 4; mt++)
        #pragma unroll
        for (int nt = 0; nt < 4; nt++)
            #pragma unroll
            for (int e = 0; e < 4; e++) c[mt][nt][e] = 0.f;

    int nT = (K + TBK - 1) / TBK;

    auto issue = [&](int kt) {
        int st = kt & 1;
        #pragma unroll
        for (int e = 0; e < 4; e++) {
            int idx = e * 256 + tid;
            int r = idx >> 3, cc = idx & 7;
            int kcol = kt * TBK + cc * 4;
            int vb = (kcol + 4 <= K) ? 16 : 0;
            int kc = vb ? kcol : 0;
            cp_async16(smem_u32(&As[(st*TBM + r)*TPAD + cc*4]),
                       A + (size_t)(bm + r) * K + kc, vb);
            int brow = bn + r;
            int bb = (brow < N) ? vb : 0;
            int br = (brow < N) ? brow : 0;
            cp_async16(smem_u32(&Bs[(st*TBM + r)*TPAD + cc*4]),
                       Bw + (size_t)br * K + kc, bb);
        }
        asm volatile("cp.async.commit_group;");
    };

    issue(0);

    int ar = lane >> 2, ac = lane & 3;
    for (int kt = 0; kt < nT; kt++) {
        if (kt + 1 < nT) issue(kt + 1);
        else asm volatile("cp.async.commit_group;");
        asm volatile("cp.async.wait_group 1;");
        __syncthreads();
        int buf = kt & 1;
        const uint32_t* uA = reinterpret_cast<const uint32_t*>(As + buf*TBM*TPAD);
        const uint32_t* uB = reinterpret_cast<const uint32_t*>(Bs + buf*TBM*TPAD);
        #pragma unroll
        for (int ks = 0; ks < 4; ks++) {
            int k0 = ks * 8;
            uint32_t af[4][4], bf[4][2];
            #pragma unroll
            for (int mt = 0; mt < 4; mt++) {
                int rb = m_warp + mt * 16;
                af[mt][0] = uA[(rb + ar)*TPAD + k0 + ac];
                af[mt][1] = uA[(rb + ar + 8)*TPAD + k0 + ac];
                af[mt][2] = uA[(rb + ar)*TPAD + k0 + ac + 4];
                af[mt][3] = uA[(rb + ar + 8)*TPAD + k0 + ac + 4];
            }
            #pragma unroll
            for (int nt = 0; nt < 4; nt++) {
                int nb = n_warp + nt * 8;
                bf[nt][0] = uB[(nb + ar)*TPAD + k0 + ac];
                bf[nt][1] = uB[(nb + ar)*TPAD + k0 + ac + 4];
            }
            #pragma unroll
            for (int mt = 0; mt < 4; mt++)
                #pragma unroll
                for (int nt = 0; nt < 4; nt++)
                    mma_tf32(c[mt][nt], af[mt], bf[nt]);
        }
        __syncthreads();
    }

    int cr = lane >> 2, cc = (lane & 3) * 2;
    #pragma unroll
    for (int mt = 0; mt < 4; mt++) {
        size_t r0 = (size_t)(bm + m_warp + mt * 16 + cr);
        #pragma unroll
        for (int nt = 0; nt < 4; nt++) {
            int col = bn + n_warp + nt * 8 + cc;
            if (col < N) {
                float v0 = c[mt][nt][0], v1 = c[mt][nt][1];
                float v2 = c[mt][nt][2], v3 = c[mt][nt][3];
                if (GELU) {
                    float b0v = bias[col], b1v = bias[col + 1];
                    v0 += b0v; v1 += b1v; v2 += b0v; v3 += b1v;
                    v0 = 0.5f * v0 * (1.0f + erff(v0 * 0.70710678118654752f));
                    v1 = 0.5f * v1 * (1.0f + erff(v1 * 0.70710678118654752f));
                    v2 = 0.5f * v2 * (1.0f + erff(v2 * 0.70710678118654752f));
                    v3 = 0.5f * v3 * (1.0f + erff(v3 * 0.70710678118654752f));
                }
                *reinterpret_cast<float2*>(C + r0 * N + col) = make_float2(v0, v1);
                *reinterpret_cast<float2*>(C + (r0 + 8) * N + col) = make_float2(v2, v3);
            }
        }
    }
}

// ---------------- beta = sigmoid(hs @ Wb^T) ----------------
__global__ __launch_bounds__(128) void beta_kernel(const float* __restrict__ hs,
                                                   const float* __restrict__ Wb)
{
    int row = blockIdx.x;
    int w = threadIdx.x >> 5, lane = threadIdx.x & 31;
    const float* xr = hs + (size_t)row * DD;
    const float* wr = Wb + (size_t)w * DD;
    float acc = 0.f;
    for (int d = lane; d < DD; d += 32) acc += xr[d] * wr[d];
    acc = wred_sum(acc);
    if (lane == 0) g_beta[row * HH + w] = 1.f / (1.f + __expf(-acc));
}

// ---------------- delta stage A: fused q/k/v dwconv+silu (float4), 2-row blocking + d-split ----------------
#define PADA 260
#define SA_QS 0
#define SA_KS (32*PADA)
#define SA_AT (64*PADA)
#define SA_BE (64*PADA + 1056)
#define SA_RN (64*PADA + 1088)
#define SA_SC (64*PADA + 1152)
#define SA_FLOATS (64*PADA + 1152 + 1024)
__global__ __launch_bounds__(256) void stageA_kernel(const float* __restrict__ wq_conv,
                                                     const float* __restrict__ wk_conv,
                                                     const float* __restrict__ wv_conv)
{
    extern __shared__ float sm[];
    float* q_s  = sm + SA_QS;
    float* k_s  = sm + SA_KS;
    float* attn = sm + SA_AT;
    float* be_s = sm + SA_BE;
    float* rn_s = sm + SA_RN;
    float* sc_s = sm + SA_SC;

    int t = threadIdx.x;
    int ci = blockIdx.x, h = blockIdx.y, b = blockIdx.z;
    size_t rowbase = (size_t)b * LL + (size_t)ci * 32;
    size_t col0 = (size_t)h * DV;

    int dhalf = t >> 7;
    int tt = t & 127;
    int i0 = tt >> 3;
    int jg = tt & 7;
    int dbase = dhalf * 128;

    // fused causal conv K=4 + silu for q,k,v (float4 tile: 4 cols x 8 rows + 3-row halo)
    {
        int c4 = (t & 63) * 4;          // 0..252 within head
        int rb = t >> 6;                // 0..3 row block
        int cg = (int)col0 + c4;
        int lbase = ci * 32 + rb * 8 - 3;          // local seq index of buf[0]
        long long gbase = (long long)rowbase + rb * 8 - 3;

        float4 buf[11];
        // ---- q ----
        {
            float4 w0 = *reinterpret_cast<const float4*>(&wq_conv[(cg+0)*4]);
            float4 w1 = *reinterpret_cast<const float4*>(&wq_conv[(cg+1)*4]);
            float4 w2 = *reinterpret_cast<const float4*>(&wq_conv[(cg+2)*4]);
            float4 w3 = *reinterpret_cast<const float4*>(&wq_conv[(cg+3)*4]);
            #pragma unroll
            for (int j = 0; j < 11; j++) {
                buf[j] = make_float4(0.f,0.f,0.f,0.f);
                if (lbase + j >= 0)
                    buf[j] = *reinterpret_cast<const float4*>(&g_qlin[(size_t)(gbase + j) * DD + cg]);
            }
            #pragma unroll
            for (int i = 0; i < 8; i++) {
                float ax = 0.f, ay = 0.f, az = 0.f, aw = 0.f;
                ax = fmaf(buf[i].x,   w0.x, ax); ax = fmaf(buf[i+1].x, w0.y, ax);
                ax = fmaf(buf[i+2].x, w0.z, ax); ax = fmaf(buf[i+3].x, w0.w, ax);
                ay = fmaf(buf[i].y,   w1.x, ay); ay = fmaf(buf[i+1].y, w1.y, ay);
                ay = fmaf(buf[i+2].y, w1.z, ay); ay = fmaf(buf[i+3].y, w1.w, ay);
                az = fmaf(buf[i].z,   w2.x, az); az = fmaf(buf[i+1].z, w2.y, az);
                az = fmaf(buf[i+2].z, w2.z, az); az = fmaf(buf[i+3].z, w2.w, az);
                aw = fmaf(buf[i].w,   w3.x, aw); aw = fmaf(buf[i+1].w, w3.y, aw);
                aw = fmaf(buf[i+2].w, w3.z, aw); aw = fmaf(buf[i+3].w, w3.w, aw);
                ax = ax / (1.f + __expf(-ax));
                ay = ay / (1.f + __expf(-ay));
                az = az / (1.f + __expf(-az));
                aw = aw / (1.f + __expf(-aw));
                *reinterpret_cast<float4*>(&q_s[(rb*8+i)*PADA + c4]) = make_float4(ax, ay, az, aw);
            }
        }
        // ---- k ----
        {
            float4 w0 = *reinterpret_cast<const float4*>(&wk_conv[(cg+0)*4]);
            float4 w1 = *reinterpret_cast<const float4*>(&wk_conv[(cg+1)*4]);
            float4 w2 = *reinterpret_cast<const float4*>(&wk_conv[(cg+2)*4]);
            float4 w3 = *reinterpret_cast<const float4*>(&wk_conv[(cg+3)*4]);
            #pragma unroll
            for (int j = 0; j < 11; j++) {
                buf[j] = make_float4(0.f,0.f,0.f,0.f);
                if (lbase + j >= 0)
                    buf[j] = *reinterpret_cast<const float4*>(&g_klin[(size_t)(gbase + j) * DD + cg]);
            }
            #pragma unroll
            for (int i = 0; i < 8; i++) {
                float ax = 0.f, ay = 0.f, az = 0.f, aw = 0.f;
                ax = fmaf(buf[i].x,   w0.x, ax); ax = fmaf(buf[i+1].x, w0.y, ax);
                ax = fmaf(buf[i+2].x, w0.z, ax); ax = fmaf(buf[i+3].x, w0.w, ax);
                ay = fmaf(buf[i].y,   w1.x, ay); ay = fmaf(buf[i+1].y, w1.y, ay);
                ay = fmaf(buf[i+2].y, w1.z, ay); ay = fmaf(buf[i+3].y, w1.w, ay);
                az = fmaf(buf[i].z,   w2.x, az); az = fmaf(buf[i+1].z, w2.y, az);
                az = fmaf(buf[i+2].z, w2.z, az); az = fmaf(buf[i+3].z, w2.w, az);
                aw = fmaf(buf[i].w,   w3.x, aw); aw = fmaf(buf[i+1].w, w3.y, aw);
                aw = fmaf(buf[i+2].w, w3.z, aw); aw = fmaf(buf[i+3].w, w3.w, aw);
                ax = ax / (1.f + __expf(-ax));
                ay = ay / (1.f + __expf(-ay));
                az = az / (1.f + __expf(-az));
                aw = aw / (1.f + __expf(-aw));
                *reinterpret_cast<float4*>(&k_s[(rb*8+i)*PADA + c4]) = make_float4(ax, ay, az, aw);
            }
        }
        // ---- v (writes g_v for later v*beta use and for stageB FIR) ----
        {
            float4 w0 = *reinterpret_cast<const float4*>(&wv_conv[(cg+0)*4]);
            float4 w1 = *reinterpret_cast<const float4*>(&wv_conv[(cg+1)*4]);
            float4 w2 = *reinterpret_cast<const float4*>(&wv_conv[(cg+2)*4]);
            float4 w3 = *reinterpret_cast<const float4*>(&wv_conv[(cg+3)*4]);
            #pragma unroll
            for (int j = 0; j < 11; j++) {
                buf[j] = make_float4(0.f,0.f,0.f,0.f);
                if (lbase + j >= 0)
                    buf[j] = *reinterpret_cast<const float4*>(&g_vlin[(size_t)(gbase + j) * DD + cg]);
            }
            #pragma unroll
            for (int i = 0; i < 8; i++) {
                float ax = 0.f, ay = 0.f, az = 0.f, aw = 0.f;
                ax = fmaf(buf[i].x,   w0.x, ax); ax = fmaf(buf[i+1].x, w0.y, ax);
                ax = fmaf(buf[i+2].x, w0.z, ax); ax = fmaf(buf[i+3].x, w0.w, ax);
                ay = fmaf(buf[i].y,   w1.x, ay); ay = fmaf(buf[i+1].y, w1.y, ay);
                ay = fmaf(buf[i+2].y, w1.z, ay); ay = fmaf(buf[i+3].y, w1.w, ay);
                az = fmaf(buf[i].z,   w2.x, az); az = fmaf(buf[i+1].z, w2.y, az);
                az = fmaf(buf[i+2].z, w2.z, az); az = fmaf(buf[i+3].z, w2.w, az);
                aw = fmaf(buf[i].w,   w3.x, aw); aw = fmaf(buf[i+1].w, w3.y, aw);
                aw = fmaf(buf[i+2].w, w3.z, aw); aw = fmaf(buf[i+3].w, w3.w, aw);
                ax = ax / (1.f + __expf(-ax));
                ay = ay / (1.f + __expf(-ay));
                az = az / (1.f + __expf(-az));
                aw = aw / (1.f + __expf(-aw));
                *reinterpret_cast<float4*>(&g_v[(rowbase + rb*8 + i) * DD + cg]) =
                    make_float4(ax, ay, az, aw);
            }
        }
    }
    if (t < 32) be_s[t] = g_beta[(rowbase + t) * HH + h];
    __syncthreads();

    {
        int r = t >> 3, g = t & 7;
        float sq = 0.f, sk = 0.f;
        #pragma unroll
        for (int dd = 0; dd < 32; dd++) {
            float a = q_s[r*PADA + g + 8*dd]; sq += a*a;
            float c2 = k_s[r*PADA + g + 8*dd]; sk += c2*c2;
        }
        #pragma unroll
        for (int o = 4; o > 0; o >>= 1) {
            sq += __shfl_xor_sync(0xffffffffu, sq, o);
            sk += __shfl_xor_sync(0xffffffffu, sk, o);
        }
        if (g == 0) { rn_s[r] = rsqrtf(sq + 1e-12f); rn_s[32+r] = rsqrtf(sk + 1e-12f); }
    }
    __syncthreads();
    #pragma unroll
    for (int e = 0; e < 8; e++) {
        int idx = e*256 + t;
        int i = idx >> 6, c = (idx & 63) * 4;
        float rq = rn_s[i], rk = rn_s[32+i];
        float4 qv = *reinterpret_cast<float4*>(&q_s[i*PADA + c]);
        qv.x *= rq; qv.y *= rq; qv.z *= rq; qv.w *= rq;
        *reinterpret_cast<float4*>(&q_s[i*PADA + c]) = qv;
        float4 kv = *reinterpret_cast<float4*>(&k_s[i*PADA + c]);
        kv.x *= rk; kv.y *= rk; kv.z *= rk; kv.w *= rk;
        *reinterpret_cast<float4*>(&k_s[i*PADA + c]) = kv;
    }
    __syncthreads();

    size_t chbase = (((size_t)b * HH + h) * NC + ci) * (32 * DV);
    size_t labase = (((size_t)b * HH + h) * NC + ci) * 1024;

    {
        float acc0[4] = {0.f,0.f,0.f,0.f};
        float acc1[4] = {0.f,0.f,0.f,0.f};
        for (int d = 0; d < 128; d += 4) {
            float4 q0 = *reinterpret_cast<const float4*>(&q_s[i0*PADA + dbase + d]);
            float4 q1 = *reinterpret_cast<const float4*>(&q_s[(i0+16)*PADA + dbase + d]);
            #pragma unroll
            for (int jj = 0; jj < 4; jj++) {
                float4 kv = *reinterpret_cast<const float4*>(&k_s[(jg + 8*jj)*PADA + dbase + d]);
                acc0[jj] = fmaf(q0.x, kv.x, acc0[jj]);
                acc0[jj] = fmaf(q0.y, kv.y, acc0[jj]);
                acc0[jj] = fmaf(q0.z, kv.z, acc0[jj]);
                acc0[jj] = fmaf(q0.w, kv.w, acc0[jj]);
                acc1[jj] = fmaf(q1.x, kv.x, acc1[jj]);
                acc1[jj] = fmaf(q1.y, kv.y, acc1[jj]);
                acc1[jj] = fmaf(q1.z, kv.z, acc1[jj]);
                acc1[jj] = fmaf(q1.w, kv.w, acc1[jj]);
            }
        }
        if (dhalf == 1) {
            #pragma unroll
            for (int jj = 0; jj < 4; jj++) {
                sc_s[tt*8 + jj]     = acc0[jj];
                sc_s[tt*8 + 4 + jj] = acc1[jj];
            }
        }
        __syncthreads();
        if (dhalf == 0) {
            #pragma unroll
            for (int jj = 0; jj < 4; jj++) {
                float v0 = acc0[jj] + sc_s[tt*8 + jj];
                float v1 = acc1[jj] + sc_s[tt*8 + 4 + jj];
                int j = jg + 8*jj;
                g_la[labase + i0*32 + j]      = (j <= i0)      ? v0 : 0.f;
                g_la[labase + (i0+16)*32 + j] = (j <= i0 + 16) ? v1 : 0.f;
            }
        }
    }
    __syncthreads();

    #pragma unroll
    for (int e = 0; e < 8; e++) {
        int idx = e*256 + t;
        int i = idx >> 6, c = (idx & 63) * 4;
        *reinterpret_cast<float4*>(&g_qn[chbase + i*DV + c]) =
            *reinterpret_cast<const float4*>(&q_s[i*PADA + c]);
        *reinterpret_cast<float4*>(&g_kn[chbase + i*DV + c]) =
            *reinterpret_cast<const float4*>(&k_s[i*PADA + c]);
        float4 vv = *reinterpret_cast<const float4*>(&g_v[(rowbase+i)*DD + col0 + c]);
        float be = be_s[i];
        vv.x *= be; vv.y *= be; vv.z *= be; vv.w *= be;
        *reinterpret_cast<float4*>(&q_s[i*PADA + c]) = vv;
    }
    __syncthreads();

    {
        float bi0 = be_s[i0], bi1 = be_s[i0 + 16];
        float acc0[4] = {0.f,0.f,0.f,0.f};
        float acc1[4] = {0.f,0.f,0.f,0.f};
        for (int d = 0; d < 128; d += 4) {
            float4 k0v = *reinterpret_cast<const float4*>(&k_s[i0*PADA + dbase + d]);
            k0v.x *= bi0; k0v.y *= bi0; k0v.z *= bi0; k0v.w *= bi0;
            float4 k1v = *reinterpret_cast<const float4*>(&k_s[(i0+16)*PADA + dbase + d]);
            k1v.x *= bi1; k1v.y *= bi1; k1v.z *= bi1; k1v.w *= bi1;
            #pragma unroll
            for (int jj = 0; jj < 4; jj++) {
                float4 kv = *reinterpret_cast<const float4*>(&k_s[(jg + 8*jj)*PADA + dbase + d]);
                acc0[jj] = fmaf(k0v.x, kv.x, acc0[jj]);
                acc0[jj] = fmaf(k0v.y, kv.y, acc0[jj]);
                acc0[jj] = fmaf(k0v.z, kv.z, acc0[jj]);
                acc0[jj] = fmaf(k0v.w, kv.w, acc0[jj]);
                acc1[jj] = fmaf(k1v.x, kv.x, acc1[jj]);
                acc1[jj] = fmaf(k1v.y, kv.y, acc1[jj]);
                acc1[jj] = fmaf(k1v.z, kv.z, acc1[jj]);
                acc1[jj] = fmaf(k1v.w, kv.w, acc1[jj]);
            }
        }
        if (dhalf == 1) {
            #pragma unroll
            for (int jj = 0; jj < 4; jj++) {
                sc_s[tt*8 + jj]     = acc0[jj];
                sc_s[tt*8 + 4 + jj] = acc1[jj];
            }
        }
        __syncthreads();
        if (dhalf == 0) {
            #pragma unroll
            for (int jj = 0; jj < 4; jj++) {
                float v0 = acc0[jj] + sc_s[tt*8 + jj];
                float v1 = acc1[jj] + sc_s[tt*8 + 4 + jj];
                int j = jg + 8*jj;
                attn[i0*33 + j]      = (i0 > j)      ? -v0 : 0.f;
                attn[(i0+16)*33 + j] = (i0 + 16 > j) ? -v1 : 0.f;
            }
        }
    }
    __syncthreads();

    if (t < 32) {
        int j = t;
        for (int i = 1; i < 32; i++) {
            float upd = 0.f;
            if (j < i)
                for (int k = j + 1; k < i; k++) upd += attn[i*33 + k] * attn[k*33 + j];
            __syncwarp();
            if (j < i) attn[i*33 + j] += upd;
            __syncwarp();
        }
        attn[j*33 + j] = 1.f;
    }
    __syncthreads();

    {
        int i = t >> 3, g = t & 7;
        float2 accu[16];
        #pragma unroll
        for (int dd = 0; dd < 16; dd++) accu[dd] = make_float2(0.f, 0.f);
        for (int k = 0; k < 32; k++) {
            float av = attn[i*33 + k];
            #pragma unroll
            for (int dd = 0; dd < 16; dd++) {
                float2 qv = *reinterpret_cast<const float2*>(&q_s[k*PADA + g*2 + dd*16]);
                accu[dd].x = fmaf(av, qv.x, accu[dd].x);
                accu[dd].y = fmaf(av, qv.y, accu[dd].y);
            }
        }
        #pragma unroll
        for (int dd = 0; dd < 16; dd++)
            *reinterpret_cast<float2*>(&g_u[chbase + i*DV + g*2 + dd*16]) = accu[dd];

        #pragma unroll
        for (int dd = 0; dd < 16; dd++) accu[dd] = make_float2(0.f, 0.f);
        for (int k = 0; k < 32; k++) {
            float av = attn[i*33 + k] * be_s[k];
            #pragma unroll
            for (int dd = 0; dd < 16; dd++) {
                float2 kv = *reinterpret_cast<const float2*>(&k_s[k*PADA + g*2 + dd*16]);
                accu[dd].x = fmaf(av, kv.x, accu[dd].x);
                accu[dd].y = fmaf(av, kv.y, accu[dd].y);
            }
        }
        #pragma unroll
        for (int dd = 0; dd < 16; dd++)
            *reinterpret_cast<float2*>(&g_w[chbase + i*DV + g*2 + dd*16]) = accu[dd];
    }
}

// ---------------- delta stage B + fused FIR/copy (512 threads) ----------------
#define SBW 264
#define SB2_W   0
#define SB2_Q   8448
#define SB2_K   16896
#define SB2_LA  25344
#define SB2_BUF 26368
#define SB2_S   52736
#define SB2_UI  57344
#define SB2_FLOATS 57856
#define BAR_SCAN() asm volatile("bar.sync 1, 256;" ::: "memory")

__global__ __launch_bounds__(512) void stageB_kernel(
    const float* __restrict__ w3, const float* __restrict__ w7,
    const float* __restrict__ w25, const float* __restrict__ w1,
    const float* __restrict__ hs)
{
    extern __shared__ float sm[];
    int t = threadIdx.x;
    int js = blockIdx.x, h = blockIdx.y, b = blockIdx.z;

    if (t >= 256) {
        int lt = t - 256;
        int blockLin = js + 16 * h + 64 * b;
        int rbase = blockLin * 64;

        for (int r = 0; r < 64; r++) {
            int row = rbase + r;
            *reinterpret_cast<float4*>(&g_rin[(size_t)row * RIN + lt*4]) =
                *reinterpret_cast<const float4*>(&hs[(size_t)row * DD + lt*4]);
        }

        for (int cho = 0; cho < 4; cho++) {
            int c = cho * 256 + lt;
            float fw3[3], fw7[7], fw25[25], fw1;
            #pragma unroll
            for (int j = 0; j < 3; j++)  fw3[j]  = w3[c*3 + j];
            #pragma unroll
            for (int j = 0; j < 7; j++)  fw7[j]  = w7[c*7 + j];
            #pragma unroll
            for (int j = 0; j < 25; j++) fw25[j] = w25[c*25 + j];
            fw1 = w1[c];
            for (int r = 0; r < 64; r++) {
                int row = rbase + r;
                int l = row & (LL - 1);
                float x[25];
                #pragma unroll
                for (int tt = 0; tt < 25; tt++)
                    x[tt] = (l - tt >= 0) ? g_v[(size_t)(row - tt) * DD + c] : 0.f;
                float a3 = 0.f, a7 = 0.f, a25 = 0.f;
                #pragma unroll
                for (int j = 0; j < 3; j++)  a3  += fw3[j]  * x[2  - j];
                #pragma unroll
                for (int j = 0; j < 7; j++)  a7  += fw7[j]  * x[6  - j];
                #pragma unroll
                for (int j = 0; j < 25; j++) a25 += fw25[j] * x[24 - j];
                size_t oi = (size_t)row * DD + c;
                g_br0[oi] = a3;
                g_br1[oi] = a7;
                g_br2[oi] = a25;
                g_br4[oi] = fw1 * x[0];
            }
        }
        return;
    }

    float* S  = sm + SB2_S;
    float* ui = sm + SB2_UI;

    #pragma unroll
    for (int j = 0; j < 16; j++) S[t*18 + j] = 0.f;
    size_t bh = (size_t)b * HH + h;
    int ii = t >> 3, jc = t & 7;

    auto issue_chunk = [&](int ci) {
        float* buf = sm + (ci & 1) * SB2_BUF;
        size_t chb = (bh * NC + ci) * (32 * DV);
        #pragma unroll
        for (int e = 0; e < 8; e++) {
            int idx = e * 256 + t;
            int i = idx >> 6, cc = idx & 63;
            int goff = idx * 4;
            int soff = i * SBW + cc * 4;
            cp_async16(smem_u32(&buf[SB2_W + soff]), g_w  + chb + goff, 16);
            cp_async16(smem_u32(&buf[SB2_Q + soff]), g_qn + chb + goff, 16);
            cp_async16(smem_u32(&buf[SB2_K + soff]), g_kn + chb + goff, 16);
        }
        cp_async16(smem_u32(&buf[SB2_LA + t*4]), g_la + (bh * NC + ci) * 1024 + t*4, 16);
        asm volatile("cp.async.commit_group;");
    };

    issue_chunk(0);
    issue_chunk(1);
    float2 uv = *reinterpret_cast<const float2*>(
        &g_u[(bh * NC + 0) * (32 * DV) + (size_t)ii * DV + js*16 + 2*jc]);

    for (int ci = 0; ci < NC; ci++) {
        asm volatile("cp.async.wait_group %0;" :: "n"(1));
        BAR_SCAN();
        float* buf  = sm + (ci & 1) * SB2_BUF;
        float* w_s  = buf + SB2_W;
        float* q_s  = buf + SB2_Q;
        float* k_s  = buf + SB2_K;
        float* la_s = buf + SB2_LA;

        float2 uv_next = make_float2(0.f, 0.f);
        if (ci + 1 < NC)
            uv_next = *reinterpret_cast<const float2*>(
                &g_u[(bh * NC + ci + 1) * (32 * DV) + (size_t)ii * DV + js*16 + 2*jc]);

        float a0 = uv.x, a1 = uv.y, o0 = 0.f, o1 = 0.f;
        #pragma unroll 4
        for (int m = 0; m < 256; m += 2) {
            float2 wv = *reinterpret_cast<const float2*>(&w_s[ii*SBW + m]);
            float2 qv = *reinterpret_cast<const float2*>(&q_s[ii*SBW + m]);
            float2 s0 = *reinterpret_cast<const float2*>(&S[m*18 + 2*jc]);
            float2 s1 = *reinterpret_cast<const float2*>(&S[(m+1)*18 + 2*jc]);
            a0 = fmaf(-wv.x, s0.x, a0); a1 = fmaf(-wv.x, s0.y, a1);
            o0 = fmaf( qv.x, s0.x, o0); o1 = fmaf( qv.x, s0.y, o1);
            a0 = fmaf(-wv.y, s1.x, a0); a1 = fmaf(-wv.y, s1.y, a1);
            o0 = fmaf( qv.y, s1.x, o0); o1 = fmaf( qv.y, s1.y, o1);
        }
        ui[ii*16 + 2*jc]     = a0;
        ui[ii*16 + 2*jc + 1] = a1;
        BAR_SCAN();

        #pragma unroll
        for (int k = 0; k < 32; k++) {
            float lv = la_s[ii*32 + k];
            float2 uu = *reinterpret_cast<const float2*>(&ui[k*16 + 2*jc]);
            o0 = fmaf(lv, uu.x, o0); o1 = fmaf(lv, uu.y, o1);
        }
        size_t orow = ((size_t)b * LL + (size_t)ci*32 + ii) * DD + (size_t)h * DV + js*16 + 2*jc;
        *reinterpret_cast<float2*>(&g_br3[orow]) = make_float2(o0, o1);

        float acc[16];
        #pragma unroll
        for (int j = 0; j < 16; j++) acc[j] = 0.f;
        #pragma unroll 4
        for (int i = 0; i < 32; i++) {
            float kv = k_s[i*SBW + t];
            const float4* up = reinterpret_cast<const float4*>(&ui[i*16]);
            float4 u0 = up[0], u1 = up[1], u2 = up[2], u3 = up[3];
            acc[0]  = fmaf(kv, u0.x, acc[0]);  acc[1]  = fmaf(kv, u0.y, acc[1]);
            acc[2]  = fmaf(kv, u0.z, acc[2]);  acc[3]  = fmaf(kv, u0.w, acc[3]);
            acc[4]  = fmaf(kv, u1.x, acc[4]);  acc[5]  = fmaf(kv, u1.y, acc[5]);
            acc[6]  = fmaf(kv, u1.z, acc[6]);  acc[7]  = fmaf(kv, u1.w, acc[7]);
            acc[8]  = fmaf(kv, u2.x, acc[8]);  acc[9]  = fmaf(kv, u2.y, acc[9]);
            acc[10] = fmaf(kv, u2.z, acc[10]); acc[11] = fmaf(kv, u2.w, acc[11]);
            acc[12] = fmaf(kv, u3.x, acc[12]); acc[13] = fmaf(kv, u3.y, acc[13]);
            acc[14] = fmaf(kv, u3.z, acc[14]); acc[15] = fmaf(kv, u3.w, acc[15]);
        }
        #pragma unroll
        for (int j = 0; j < 16; j++) S[t*18 + j] += acc[j];

        BAR_SCAN();
        if (ci + 2 < NC) issue_chunk(ci + 2);
        else asm volatile("cp.async.commit_group;");
        uv = uv_next;
    }
}

// ---------------- branch stats (float4 loads) ----------------
__global__ __launch_bounds__(256) void stats_kernel()
{
    int gw = blockIdx.x * 8 + (threadIdx.x >> 5);
    int lane = threadIdx.x & 31;
    int row = gw >> 2, h = gw & 3;
    size_t base = (size_t)row * DD + (size_t)h * DV + lane * 8;
    float x[5][8];
    #pragma unroll
    for (int p = 0; p < 5; p++) {
        const float* bp = branch_ptr(p);
        float4 a = *reinterpret_cast<const float4*>(&bp[base]);
        float4 bq = *reinterpret_cast<const float4*>(&bp[base + 4]);
        x[p][0]=a.x; x[p][1]=a.y; x[p][2]=a.z; x[p][3]=a.w;
        x[p][4]=bq.x; x[p][5]=bq.y; x[p][6]=bq.z; x[p][7]=bq.w;
    }
    float ssv[5];
    float* rout = g_rin + (size_t)row * RIN;
    #pragma unroll
    for (int p = 0; p < 5; p++) {
        float s = 0.f, ss = 0.f, mx = -1e30f;
        #pragma unroll
        for (int e = 0; e < 8; e++) {
            float v = x[p][e];
            s += v; ss += v*v; mx = fmaxf(mx, v);
        }
        s = wred_sum(s); ss = wred_sum(ss); mx = wred_max(mx);
        float ez[8]; float Zp = 0.f;
        #pragma unroll
        for (int e = 0; e < 8; e++) { ez[e] = __expf(x[p][e] - mx); Zp += ez[e]; }
        float Z = wred_sum(Zp);
        float ep = 0.f;
        #pragma unroll
        for (int e = 0; e < 8; e++) { float smv = ez[e] / Z; ep += smv * __logf(smv + 1e-8f); }
        float ent = -wred_sum(ep);
        ssv[p] = ss;
        if (lane == 0) {
            rout[1024 + (p*4 + 0)*HH + h] = s * (1.f/256.f);
            rout[1024 + (p*4 + 1)*HH + h] = (ss - s*s*(1.f/256.f)) * (1.f/255.f);
            rout[1024 + (p*4 + 2)*HH + h] = mx;
            rout[1024 + (p*4 + 3)*HH + h] = ent;
        }
    }
    int c = 0;
    #pragma unroll
    for (int i = 0; i < 5; i++)
        #pragma unroll
        for (int j = i + 1; j < 5; j++) {
            float d = 0.f;
            #pragma unroll
            for (int e = 0; e < 8; e++) d += x[i][e] * x[j][e];
            d = wred_sum(d);
            if (lane == 0)
                rout[1104 + c*HH + h] = d / (sqrtf(ssv[i]) * sqrtf(ssv[j]) + 1e-8f);
            c++;
        }
}

// ---------------- logits + softmax floor + mix + RMSnorm : 8 rows per block ----------------
#define LMR 8
#define HPAD 2292
#define LM_SMEM (LMR*HPAD*4)
__global__ __launch_bounds__(256) void logits_mix_kernel(const float* __restrict__ W2,
                                                         const float* __restrict__ b2,
                                                         const float* __restrict__ norm_w)
{
    extern __shared__ float lsm[];
    __shared__ float lg_s[LMR][20];
    __shared__ float pr_s[LMR][20];
    __shared__ float wred_s[LMR][8];
    int t = threadIdx.x;
    int wid = t >> 5, lane = t & 31;
    int row0 = blockIdx.x * LMR;

    for (int idx = t; idx < LMR * 572; idx += 256) {
        int r = idx / 572, c4 = idx % 572;
        *reinterpret_cast<float4*>(&lsm[r*HPAD + c4*4]) =
            *reinterpret_cast<const float4*>(&g_hrt[(size_t)(row0 + r) * RH + c4*4]);
    }
    __syncthreads();

    {
        const float* hr = &lsm[wid*HPAD];
        for (int n = 0; n < 20; n++) {
            const float* w2r = W2 + (size_t)n * RH;
            float acc = 0.f;
            for (int idx = lane; idx < 572; idx += 32) {
                float4 hv = *reinterpret_cast<const float4*>(&hr[idx*4]);
                float4 wv = *reinterpret_cast<const float4*>(&w2r[idx*4]);
                acc += hv.x*wv.x + hv.y*wv.y + hv.z*wv.z + hv.w*wv.w;
            }
            acc = wred_sum(acc);
            if (lane == 0) lg_s[wid][n] = acc + b2[n];
        }
    }
    __syncthreads();
    if (t < 32) {
        int r = t >> 2, hh = t & 3;
        float m = -1e30f;
        #pragma unroll
        for (int p = 0; p < 5; p++) m = fmaxf(m, lg_s[r][hh*5 + p]);
        float Z = 0.f, e[5];
        #pragma unroll
        for (int p = 0; p < 5; p++) { e[p] = __expf(lg_s[r][hh*5 + p] - m); Z += e[p]; }
        #pragma unroll
        for (int p = 0; p < 5; p++) pr_s[r][hh*5 + p] = e[p] / Z * 0.95f + 0.01f;
    }
    __syncthreads();

    int c = t * 4;
    int hh = t >> 6;
    float4 nw4 = *reinterpret_cast<const float4*>(&norm_w[c & 255]);
    float4 val[LMR];
    #pragma unroll
    for (int r = 0; r < LMR; r++) {
        size_t base = (size_t)(row0 + r) * DD + c;
        float4 acc = make_float4(0.f,0.f,0.f,0.f);
        #pragma unroll
        for (int p = 0; p < 5; p++) {
            float4 bv = *reinterpret_cast<const float4*>(&branch_ptr(p)[base]);
            float pr = pr_s[r][hh*5 + p];
            acc.x = fmaf(pr, bv.x, acc.x);
            acc.y = fmaf(pr, bv.y, acc.y);
            acc.z = fmaf(pr, bv.z, acc.z);
            acc.w = fmaf(pr, bv.w, acc.w);
        }
        val[r] = acc;
        float sq = acc.x*acc.x + acc.y*acc.y + acc.z*acc.z + acc.w*acc.w;
        sq = wred_sum(sq);
        if (lane == 0) wred_s[r][wid] = sq;
    }
    __syncthreads();
    #pragma unroll
    for (int r = 0; r < LMR; r++) {
        float s = wred_s[r][hh*2] + wred_s[r][hh*2 + 1];
        float rms = rsqrtf(s * (1.f/256.f) + 1e-5f);
        float4 v = val[r];
        v.x *= rms * nw4.x; v.y *= rms * nw4.y;
        v.z *= rms * nw4.z; v.w *= rms * nw4.w;
        *reinterpret_cast<float4*>(&g_mix[(size_t)(row0 + r) * DD + c]) = v;
    }
}

// ---------------- launch ----------------
static float* sym(const void* s) { void* p = nullptr; cudaGetSymbolAddress(&p, s); return (float*)p; }

extern "C" void kernel_launch(void* const* d_in, const int* in_sizes, int n_in,
                              void* d_out, int out_size)
{
    const float* hs       = (const float*)d_in[0];
    const float* Wq       = (const float*)d_in[1];
    const float* Wk       = (const float*)d_in[2];
    const float* Wv       = (const float*)d_in[3];
    const float* wq_conv  = (const float*)d_in[4];
    const float* wk_conv  = (const float*)d_in[5];
    const float* wv_conv  = (const float*)d_in[6];
    const float* Wb       = (const float*)d_in[7];
    const float* fir_s_w  = (const float*)d_in[8];
    const float* fir_m_w  = (const float*)d_in[9];
    const float* fir_l_w  = (const float*)d_in[10];
    const float* fir_id_w = (const float*)d_in[11];
    const float* W1       = (const float*)d_in[12];
    const float* b1       = (const float*)d_in[13];
    const float* W2       = (const float*)d_in[14];
    const float* b2       = (const float*)d_in[15];
    const float* norm_w   = (const float*)d_in[16];
    const float* Wo       = (const float*)d_in[17];
    float* out = (float*)d_out;

    float* p_qlin = sym(g_qlin); float* p_klin = sym(g_klin); float* p_vlin = sym(g_vlin);
    float* p_rin = sym(g_rin); float* p_hrt = sym(g_hrt); float* p_mix = sym(g_mix);

    cudaFuncSetAttribute(tf32gemm_kernel<false>, cudaFuncAttributeMaxDynamicSharedMemorySize, GEMM_SMEM);
    cudaFuncSetAttribute(tf32gemm_kernel<true>, cudaFuncAttributeMaxDynamicSharedMemorySize, GEMM_SMEM);
    cudaFuncSetAttribute(stageA_kernel, cudaFuncAttributeMaxDynamicSharedMemorySize, SA_FLOATS*4);
    cudaFuncSetAttribute(stageB_kernel, cudaFuncAttributeMaxDynamicSharedMemorySize, SB2_FLOATS*4);
    cudaFuncSetAttribute(logits_mix_kernel, cudaFuncAttributeMaxDynamicSharedMemorySize, LM_SMEM);

    beta_kernel<<<BLROWS, 128>>>(hs, Wb);
    tf32gemm_kernel<false><<<dim3(DD/TBN, BLROWS/TBM, 3), 256, GEMM_SMEM>>>(
        hs, Wq, Wk, Wv, nullptr, p_qlin, p_klin, p_vlin, BLROWS, DD, DD);

    stageA_kernel<<<dim3(NC, HH, BB), 256, SA_FLOATS*4>>>(wq_conv, wk_conv, wv_conv);
    stageB_kernel<<<dim3(16, HH, BB), 512, SB2_FLOATS*4>>>(
        fir_s_w, fir_m_w, fir_l_w, fir_id_w, hs);

    stats_kernel<<<BLROWS*HH/8, 256>>>();

    tf32gemm_kernel<true><<<dim3((RH+TBN-1)/TBN, BLROWS/TBM, 1), 256, GEMM_SMEM>>>(
        p_rin, W1, W1, W1, b1, p_hrt, p_hrt, p_hrt, BLROWS, RH, RIN);
    logits_mix_kernel<<<BLROWS/LMR, 256, LM_SMEM>>>(W2, b2, norm_w);
    tf32gemm_kernel<false><<<dim3(DD/TBN, BLROWS/TBM, 1), 256, GEMM_SMEM>>>(
        p_mix, Wo, Wo, Wo, nullptr, out, out, out, BLROWS, DD, DD);
}